// round 5
// baseline (speedup 1.0000x reference)
#include <cuda_runtime.h>
#include <cstdint>

#define BB 2
#define SS 2048
#define HH 1024
#define NH 16
#define HD 64
#define MM (BB*SS)   // 4096 rows

// Scratch (allocation is forbidden; use __device__ globals)
__device__ float    g_Wd[HH*HH];
__device__ float    g_bd[HH];
__device__ uint32_t g_DHL[(size_t)MM*2*HH];       // D, tf32 hi/lo interleaved [row][2c],[2c+1]
__device__ uint32_t g_Vt[(size_t)MM*HH];          // V, tf32, row-major
__device__ uint32_t g_VtP[(size_t)BB*NH*HD*SS];   // V^T, permuted keys, per (b,h)
__device__ float    g_C[(size_t)MM*HH];

__device__ __forceinline__ uint32_t f2tf32(float x) {
    uint32_t r;
    asm("cvt.rna.tf32.f32 %0, %1;" : "=r"(r) : "f"(x));
    return r;
}
__device__ __forceinline__ void tf32split(float x, uint32_t& hi, uint32_t& lo) {
    hi = f2tf32(x);
    lo = f2tf32(x - __uint_as_float(hi));
}
__device__ __forceinline__ void mma8(float* c,
                                     uint32_t a0, uint32_t a1, uint32_t a2, uint32_t a3,
                                     uint32_t b0, uint32_t b1) {
    asm volatile(
        "mma.sync.aligned.m16n8k8.row.col.f32.tf32.tf32.f32 "
        "{%0,%1,%2,%3}, {%4,%5,%6,%7}, {%8,%9}, {%0,%1,%2,%3};"
        : "+f"(c[0]), "+f"(c[1]), "+f"(c[2]), "+f"(c[3])
        : "r"(a0), "r"(a1), "r"(a2), "r"(a3), "r"(b0), "r"(b1));
}
__device__ __forceinline__ uint32_t smem_u32(const void* p) {
    uint32_t a;
    asm("{ .reg .u64 t; cvta.to.shared.u64 t, %1; cvt.u32.u64 %0, t; }" : "=r"(a) : "l"(p));
    return a;
}
__device__ __forceinline__ void cp16(uint32_t dst, const void* src) {
    asm volatile("cp.async.ca.shared.global [%0], [%1], 16;" :: "r"(dst), "l"(src));
}
__device__ __forceinline__ void cp_commit() { asm volatile("cp.async.commit_group;"); }
template<int N> __device__ __forceinline__ void cp_wait() {
    asm volatile("cp.async.wait_group %0;" :: "n"(N));
}

// Wd = Wq - Wk, bd = bq - bk
__global__ void sub_wb_kernel(const float* __restrict__ Wq, const float* __restrict__ Wk,
                              const float* __restrict__ bq, const float* __restrict__ bk) {
    int i = blockIdx.x * blockDim.x + threadIdx.x;
    if (i < HH*HH) g_Wd[i] = Wq[i] - Wk[i];
    if (i < HH)    g_bd[i] = bq[i] - bk[i];
}

// ---------------------------------------------------------------------------
// C = A @ W + bias.  MODE 0: fp32 out. MODE 1: tf32(uint32) out.
// MODE 2: 3xTF32 compute, hi/lo-interleaved out (g_DHL layout).
// Block 128x128, 256 threads (8 warps 2x4), warp tile 64x32, BK=16.
// ---------------------------------------------------------------------------
template<int MODE>
__global__ __launch_bounds__(256) void gemm_tc(const float* __restrict__ A,
                                               const float* __restrict__ W,
                                               const float* __restrict__ bias,
                                               void* __restrict__ Cout) {
    const bool X3 = (MODE == 2);
    const int AW = X3 ? 264 : 136;
    __shared__ uint32_t As[16 * (MODE == 2 ? 264 : 136)];
    __shared__ uint32_t Bs[16 * (MODE == 2 ? 264 : 136)];
    int tid = threadIdx.x, lane = tid & 31, w = tid >> 5;
    int la3 = lane & 3, l4 = lane >> 2;
    int wm = (w & 1) * 64, wn = (w >> 1) * 32;
    int row0 = blockIdx.y * 128, col0 = blockIdx.x * 128;

    float acc[4][4][4] = {};

    for (int k0 = 0; k0 < HH; k0 += 16) {
        __syncthreads();
        #pragma unroll
        for (int i = 0; i < 2; i++) {           // A tile 128m x 16k -> As[k][m]
            int f = tid + i * 256;
            int r = f >> 2, cg = (f & 3) * 4;
            float4 v = *(const float4*)&A[(size_t)(row0 + r) * HH + k0 + cg];
            float vv[4] = {v.x, v.y, v.z, v.w};
            if (X3) {
                #pragma unroll
                for (int j = 0; j < 4; j++) {
                    uint32_t hh, ll; tf32split(vv[j], hh, ll);
                    *(uint2*)&As[(cg + j) * AW + 2 * r] = make_uint2(hh, ll);
                }
            } else {
                #pragma unroll
                for (int j = 0; j < 4; j++) As[(cg + j) * AW + r] = f2tf32(vv[j]);
            }
        }
        #pragma unroll
        for (int i = 0; i < 2; i++) {           // B tile 16k x 128n -> Bs[k][n]
            int f = tid + i * 256;
            int r = f >> 5, cg = (f & 31) * 4;
            float4 v = *(const float4*)&W[(size_t)(k0 + r) * HH + col0 + cg];
            float vv[4] = {v.x, v.y, v.z, v.w};
            if (X3) {
                uint32_t hh[4], ll[4];
                #pragma unroll
                for (int j = 0; j < 4; j++) tf32split(vv[j], hh[j], ll[j]);
                *(uint4*)&Bs[r * AW + 2 * cg    ] = make_uint4(hh[0], ll[0], hh[1], ll[1]);
                *(uint4*)&Bs[r * AW + 2 * cg + 4] = make_uint4(hh[2], ll[2], hh[3], ll[3]);
            } else {
                #pragma unroll
                for (int j = 0; j < 4; j++) Bs[r * AW + cg + j] = f2tf32(vv[j]);
            }
        }
        __syncthreads();

        #pragma unroll
        for (int kk = 0; kk < 16; kk += 8) {
            if (X3) {
                uint32_t bh[4][2], bl[4][2];
                #pragma unroll
                for (int nt = 0; nt < 4; nt++) {
                    int n = wn + nt * 8 + l4;
                    uint2 p0 = *(const uint2*)&Bs[(kk + la3)     * AW + 2 * n];
                    uint2 p1 = *(const uint2*)&Bs[(kk + 4 + la3) * AW + 2 * n];
                    bh[nt][0] = p0.x; bl[nt][0] = p0.y;
                    bh[nt][1] = p1.x; bl[nt][1] = p1.y;
                }
                #pragma unroll
                for (int mt = 0; mt < 4; mt++) {
                    int m = wm + mt * 16 + l4;
                    uint2 a0 = *(const uint2*)&As[(kk + la3)     * AW + 2 * m];
                    uint2 a1 = *(const uint2*)&As[(kk + la3)     * AW + 2 * (m + 8)];
                    uint2 a2 = *(const uint2*)&As[(kk + 4 + la3) * AW + 2 * m];
                    uint2 a3 = *(const uint2*)&As[(kk + 4 + la3) * AW + 2 * (m + 8)];
                    #pragma unroll
                    for (int nt = 0; nt < 4; nt++) {
                        mma8(acc[mt][nt], a0.x, a1.x, a2.x, a3.x, bh[nt][0], bh[nt][1]);
                        mma8(acc[mt][nt], a0.x, a1.x, a2.x, a3.x, bl[nt][0], bl[nt][1]);
                        mma8(acc[mt][nt], a0.y, a1.y, a2.y, a3.y, bh[nt][0], bh[nt][1]);
                    }
                }
            } else {
                uint32_t bf[4][2];
                #pragma unroll
                for (int nt = 0; nt < 4; nt++) {
                    int n = wn + nt * 8 + l4;
                    bf[nt][0] = Bs[(kk + la3)     * AW + n];
                    bf[nt][1] = Bs[(kk + 4 + la3) * AW + n];
                }
                #pragma unroll
                for (int mt = 0; mt < 4; mt++) {
                    int m = wm + mt * 16 + l4;
                    uint32_t a0 = As[(kk + la3)     * AW + m];
                    uint32_t a1 = As[(kk + la3)     * AW + m + 8];
                    uint32_t a2 = As[(kk + 4 + la3) * AW + m];
                    uint32_t a3 = As[(kk + 4 + la3) * AW + m + 8];
                    #pragma unroll
                    for (int nt = 0; nt < 4; nt++)
                        mma8(acc[mt][nt], a0, a1, a2, a3, bf[nt][0], bf[nt][1]);
                }
            }
        }
    }

    #pragma unroll
    for (int mt = 0; mt < 4; mt++) {
        int r = row0 + wm + mt * 16 + l4;
        #pragma unroll
        for (int nt = 0; nt < 4; nt++) {
            int cb = col0 + wn + nt * 8 + 2 * la3;
            float v0 = acc[mt][nt][0] + bias[cb];
            float v1 = acc[mt][nt][1] + bias[cb + 1];
            float v2 = acc[mt][nt][2] + bias[cb];
            float v3 = acc[mt][nt][3] + bias[cb + 1];
            if (MODE == 0) {
                float* C = (float*)Cout;
                C[(size_t)r       * HH + cb    ] = v0;
                C[(size_t)r       * HH + cb + 1] = v1;
                C[(size_t)(r + 8) * HH + cb    ] = v2;
                C[(size_t)(r + 8) * HH + cb + 1] = v3;
            } else if (MODE == 1) {
                uint32_t* C = (uint32_t*)Cout;
                *(uint2*)&C[(size_t)r       * HH + cb] = make_uint2(f2tf32(v0), f2tf32(v1));
                *(uint2*)&C[(size_t)(r + 8) * HH + cb] = make_uint2(f2tf32(v2), f2tf32(v3));
            } else {
                uint32_t* C = (uint32_t*)Cout;
                uint32_t h0,l0,h1,l1,h2,l2,h3,l3;
                tf32split(v0, h0, l0); tf32split(v1, h1, l1);
                tf32split(v2, h2, l2); tf32split(v3, h3, l3);
                *(uint4*)&C[(size_t)r       * 2048 + 2 * cb] = make_uint4(h0, l0, h1, l1);
                *(uint4*)&C[(size_t)(r + 8) * 2048 + 2 * cb] = make_uint4(h2, l2, h3, l3);
            }
        }
    }
}

// ---------------------------------------------------------------------------
// g_Vt [B*S, H] tf32 -> g_VtP [(b,h,d), key-permuted] so PV b-fragments are
// single LDS.64: pos(s) = 8*(s>>3) + 2*(s&3) + ((s>>2)&1).
// ---------------------------------------------------------------------------
__global__ __launch_bounds__(256) void v_transpose(const uint32_t* __restrict__ Vt,
                                                   uint32_t* __restrict__ VtP) {
    __shared__ uint32_t Vs[64][65];
    int k0 = blockIdx.x * 64;
    int bh = blockIdx.y;                 // b*NH + h
    int b = bh >> 4, h = bh & 15;
    int tid = threadIdx.x;
    #pragma unroll
    for (int i = 0; i < 16; i++) {
        int idx = tid + i * 256;
        int r = idx >> 6, d = idx & 63;
        Vs[r][d] = Vt[(size_t)(b * SS + k0 + r) * HH + h * 64 + d];
    }
    __syncthreads();
    #pragma unroll
    for (int i = 0; i < 16; i++) {
        int idx = tid + i * 256;
        int d = idx >> 6, pr = idx & 63;
        int g = pr >> 3, rem = pr & 7;
        int r = g * 8 + (rem & 1) * 4 + (rem >> 1);
        VtP[(size_t)(bh * 64 + d) * SS + k0 + pr] = Vs[r][d];
    }
}

// ---------------------------------------------------------------------------
// Fused anti-causal gaussian attention (QK 3xTF32, PV tf32). Zero cvt inside.
// Block: 64 q-rows, 4 warps. K-tile 32, 2-stage cp.async double buffer.
// Smem (uint32): DkS 2x[32][136], VtS 2x[64][40], PsI [64][40] = 16384 = 64KB.
// All widths === 8 (mod 32) -> conflict-free LDS.64 per half-warp.
// ---------------------------------------------------------------------------
__global__ __launch_bounds__(128, 3) void attn_tc(const uint32_t* __restrict__ DH,
                                                  const uint32_t* __restrict__ VtP,
                                                  float* __restrict__ C) {
    extern __shared__ uint32_t sm[];
    // offsets (uint32 units)
    const int DK0 = 0;                 // 2 stages x 32*136 = 8704
    const int VT0 = 2 * 32 * 136;      // 2 stages x 64*40  = 5120
    const int PS0 = VT0 + 2 * 64 * 40; // 64*40 = 2560

    int tid = threadIdx.x, lane = tid & 31, w = tid >> 5;
    int la3 = lane & 3, l4 = lane >> 2;
    int q0 = blockIdx.x * 64, h = blockIdx.y, b = blockIdx.z;
    const uint32_t* DHb = DH + (size_t)b * SS * 2048 + h * 128;
    const uint32_t* Vb  = VtP + (size_t)(b * NH + h) * HD * SS;
    int qrow = w * 16 + l4;

    uint32_t smb = smem_u32(sm);

    // Q-side fragments: pre-split hi/lo, loaded once (loop-invariant)
    uint32_t aH[8][4], aL[8][4];
    {
        const uint32_t* r0 = DHb + (size_t)(q0 + qrow) * 2048;
        const uint32_t* r8 = r0 + (size_t)8 * 2048;
        #pragma unroll
        for (int kk8 = 0; kk8 < 8; kk8++) {
            uint2 A0 = *(const uint2*)&r0[2 * (kk8 * 8 + la3)];
            uint2 A1 = *(const uint2*)&r8[2 * (kk8 * 8 + la3)];
            uint2 A2 = *(const uint2*)&r0[2 * (kk8 * 8 + 4 + la3)];
            uint2 A3 = *(const uint2*)&r8[2 * (kk8 * 8 + 4 + la3)];
            aH[kk8][0] = A0.x; aL[kk8][0] = A0.y;
            aH[kk8][1] = A1.x; aL[kk8][1] = A1.y;
            aH[kk8][2] = A2.x; aL[kk8][2] = A2.y;
            aH[kk8][3] = A3.x; aL[kk8][3] = A3.y;
        }
    }

    float ctx[8][4] = {};
    int nT = (SS - q0) / 32;

    // stage prefetch: Dk 32 rows x 512B, V 64 rows x 128B
    #define PREFETCH(T) do {                                                     \
        int k0t = q0 + (T) * 32;                                                 \
        int st = (T) & 1;                                                        \
        uint32_t dkb = smb + (DK0 + st * 32 * 136) * 4;                          \
        uint32_t vtb = smb + (VT0 + st * 64 * 40) * 4;                           \
        _Pragma("unroll")                                                        \
        for (int i = 0; i < 8; i++) {                                            \
            int idx = tid + i * 128;                                             \
            int r = idx >> 5, j = idx & 31;                                      \
            cp16(dkb + (r * 136 + 4 * j) * 4,                                    \
                 DHb + (size_t)(k0t + r) * 2048 + 4 * j);                        \
        }                                                                        \
        _Pragma("unroll")                                                        \
        for (int i = 0; i < 4; i++) {                                            \
            int idx = tid + i * 128;                                             \
            int d = idx >> 3, j = idx & 7;                                       \
            cp16(vtb + (d * 40 + 4 * j) * 4,                                     \
                 Vb + (size_t)d * SS + k0t + 4 * j);                             \
        }                                                                        \
    } while (0)

    PREFETCH(0);
    cp_commit();

    for (int t = 0; t < nT; t++) {
        int cur = t & 1;
        __syncthreads();                       // reads of buf[cur] (iter t-2) done
        if (t + 1 < nT) PREFETCH(t + 1);
        cp_commit();
        cp_wait<1>();                          // stage t resident
        __syncthreads();

        const uint32_t* Dk = sm + DK0 + cur * 32 * 136;   // [32][136]
        const uint32_t* Vp = sm + VT0 + cur * 64 * 40;    // [64][40]
        uint32_t* Pw = sm + PS0;                          // [64][40]
        int k0 = q0 + t * 32;

        // ---- QK: S[16q x 32k], 3xTF32 ----
        float s4[4][4] = {};
        #pragma unroll
        for (int kk8 = 0; kk8 < 8; kk8++) {
            #pragma unroll
            for (int nt = 0; nt < 4; nt++) {
                const uint32_t* br = Dk + (nt * 8 + l4) * 136;
                uint2 p0 = *(const uint2*)&br[2 * (kk8 * 8 + la3)];
                uint2 p1 = *(const uint2*)&br[2 * (kk8 * 8 + 4 + la3)];
                mma8(s4[nt], aH[kk8][0], aH[kk8][1], aH[kk8][2], aH[kk8][3], p0.x, p1.x);
                mma8(s4[nt], aH[kk8][0], aH[kk8][1], aH[kk8][2], aH[kk8][3], p0.y, p1.y);
                mma8(s4[nt], aL[kk8][0], aL[kk8][1], aL[kk8][2], aL[kk8][3], p0.x, p1.x);
            }
        }

        // ---- mask (k > q strictly) + exp -> PsI (permuted cols, tf32) ----
        #pragma unroll
        for (int nt = 0; nt < 4; nt++) {
            int r8a = 2 * la3, r8b = 2 * la3 + 1;
            int posA = nt * 8 + 2 * (r8a & 3) + (r8a >> 2);
            int posB = nt * 8 + 2 * (r8b & 3) + (r8b >> 2);
            int kgA = k0 + nt * 8 + r8a;
            float p0 = (kgA     > q0 + qrow)     ? __expf(-0.5f * s4[nt][0]) : 0.0f;
            float p1 = (kgA + 1 > q0 + qrow)     ? __expf(-0.5f * s4[nt][1]) : 0.0f;
            float p2 = (kgA     > q0 + qrow + 8) ? __expf(-0.5f * s4[nt][2]) : 0.0f;
            float p3 = (kgA + 1 > q0 + qrow + 8) ? __expf(-0.5f * s4[nt][3]) : 0.0f;
            Pw[qrow * 40 + posA]       = f2tf32(p0);
            Pw[qrow * 40 + posB]       = f2tf32(p1);
            Pw[(qrow + 8) * 40 + posA] = f2tf32(p2);
            Pw[(qrow + 8) * 40 + posB] = f2tf32(p3);
        }
        __syncwarp();   // Pw rows are warp-private

        // ---- PV: ctx[16q x 64d] += P @ V over 32 keys ----
        #pragma unroll
        for (int kt = 0; kt < 4; kt++) {
            int kk = kt * 8;
            uint2 ua = *(const uint2*)&Pw[qrow * 40 + kk + 2 * la3];
            uint2 ub = *(const uint2*)&Pw[(qrow + 8) * 40 + kk + 2 * la3];
            #pragma unroll
            for (int nt = 0; nt < 8; nt++) {
                uint2 vb2 = *(const uint2*)&Vp[(nt * 8 + l4) * 40 + kk + 2 * la3];
                mma8(ctx[nt], ua.x, ub.x, ua.y, ub.y, vb2.x, vb2.y);
            }
        }
    }

    // Store ctx in merged [B,S,H] layout
    float* Cb = C + (size_t)b * SS * HH + h * HD;
    #pragma unroll
    for (int nt = 0; nt < 8; nt++) {
        int r = q0 + qrow;
        int c = nt * 8 + 2 * la3;
        Cb[(size_t)r       * HH + c    ] = ctx[nt][0];
        Cb[(size_t)r       * HH + c + 1] = ctx[nt][1];
        Cb[(size_t)(r + 8) * HH + c    ] = ctx[nt][2];
        Cb[(size_t)(r + 8) * HH + c + 1] = ctx[nt][3];
    }
}

static const int ATTN_SMEM = (2 * 32 * 136 + 2 * 64 * 40 + 64 * 40) * 4;   // 65536

extern "C" void kernel_launch(void* const* d_in, const int* in_sizes, int n_in,
                              void* d_out, int out_size) {
    const float* x  = (const float*)d_in[0];
    const float* Wq = (const float*)d_in[1];
    const float* bq = (const float*)d_in[2];
    const float* Wk = (const float*)d_in[3];
    const float* bk = (const float*)d_in[4];
    const float* Wv = (const float*)d_in[5];
    const float* bv = (const float*)d_in[6];
    const float* Wo = (const float*)d_in[7];
    const float* bo = (const float*)d_in[8];
    float* out = (float*)d_out;

    float *pWd, *pbd, *pC;
    uint32_t *pDHL, *pVt, *pVtP;
    cudaGetSymbolAddress((void**)&pWd,  g_Wd);
    cudaGetSymbolAddress((void**)&pbd,  g_bd);
    cudaGetSymbolAddress((void**)&pDHL, g_DHL);
    cudaGetSymbolAddress((void**)&pVt,  g_Vt);
    cudaGetSymbolAddress((void**)&pVtP, g_VtP);
    cudaGetSymbolAddress((void**)&pC,   g_C);

    static bool attr_set = false;
    if (!attr_set) {
        cudaFuncSetAttribute(attn_tc, cudaFuncAttributeMaxDynamicSharedMemorySize, ATTN_SMEM);
        attr_set = true;
    }

    // 1. Wd = Wq - Wk, bd = bq - bk
    sub_wb_kernel<<<(HH*HH + 255) / 256, 256>>>(Wq, Wk, bq, bk);

    // 2. D = x @ Wd + bd (3xTF32, pre-split out) ; V = x @ Wv + bv (tf32 out)
    dim3 ggrid(HH / 128, MM / 128);
    gemm_tc<2><<<ggrid, 256>>>(x, pWd, pbd, pDHL);
    gemm_tc<1><<<ggrid, 256>>>(x, Wv, bv, pVt);

    // 3. V transpose+permute for LDS.64 b-fragments
    v_transpose<<<dim3(SS / 64, BB * NH), 256>>>(pVt, pVtP);

    // 4. fused attention -> ctx in [B,S,H] layout
    dim3 agrid(SS / 64, NH, BB);
    attn_tc<<<agrid, 128, ATTN_SMEM>>>(pDHL, pVtP, pC);

    // 5. out = ctx @ Wo + bo (tf32)
    gemm_tc<0><<<ggrid, 256>>>(pC, Wo, bo, out);
}

// round 6
// speedup vs baseline: 1.0432x; 1.0432x over previous
#include <cuda_runtime.h>
#include <cstdint>

#define BB 2
#define SS 2048
#define HH 1024
#define NH 16
#define HD 64
#define MM (BB*SS)   // 4096 rows

// Scratch (allocation is forbidden; use __device__ globals)
__device__ float    g_Wd[HH*HH];
__device__ float    g_bd[HH];
__device__ uint32_t g_DHL[(size_t)MM*2*HH];       // D, tf32 hi/lo interleaved [row][2c],[2c+1]
__device__ uint32_t g_Vt[(size_t)MM*HH];          // V, tf32, row-major
__device__ uint32_t g_VtP[(size_t)BB*NH*HD*SS];   // V^T, permuted keys, per (b,h)
__device__ float    g_C[(size_t)MM*HH];

__device__ __forceinline__ uint32_t f2tf32(float x) {
    uint32_t r;
    asm("cvt.rna.tf32.f32 %0, %1;" : "=r"(r) : "f"(x));
    return r;
}
__device__ __forceinline__ void tf32split(float x, uint32_t& hi, uint32_t& lo) {
    hi = f2tf32(x);
    lo = f2tf32(x - __uint_as_float(hi));
}
__device__ __forceinline__ void mma8(float* c,
                                     uint32_t a0, uint32_t a1, uint32_t a2, uint32_t a3,
                                     uint32_t b0, uint32_t b1) {
    asm volatile(
        "mma.sync.aligned.m16n8k8.row.col.f32.tf32.tf32.f32 "
        "{%0,%1,%2,%3}, {%4,%5,%6,%7}, {%8,%9}, {%0,%1,%2,%3};"
        : "+f"(c[0]), "+f"(c[1]), "+f"(c[2]), "+f"(c[3])
        : "r"(a0), "r"(a1), "r"(a2), "r"(a3), "r"(b0), "r"(b1));
}
__device__ __forceinline__ uint32_t smem_u32(const void* p) {
    uint32_t a;
    asm("{ .reg .u64 t; cvta.to.shared.u64 t, %1; cvt.u32.u64 %0, t; }" : "=r"(a) : "l"(p));
    return a;
}
__device__ __forceinline__ void cp16(uint32_t dst, const void* src) {
    asm volatile("cp.async.ca.shared.global [%0], [%1], 16;" :: "r"(dst), "l"(src));
}
__device__ __forceinline__ void cp_commit() { asm volatile("cp.async.commit_group;"); }
template<int N> __device__ __forceinline__ void cp_wait() {
    asm volatile("cp.async.wait_group %0;" :: "n"(N));
}

// Wd = Wq - Wk, bd = bq - bk
__global__ void sub_wb_kernel(const float* __restrict__ Wq, const float* __restrict__ Wk,
                              const float* __restrict__ bq, const float* __restrict__ bk) {
    int i = blockIdx.x * blockDim.x + threadIdx.x;
    if (i < HH*HH) g_Wd[i] = Wq[i] - Wk[i];
    if (i < HH)    g_bd[i] = bq[i] - bk[i];
}

// ---------------------------------------------------------------------------
// C = A @ W + bias.  MODE 0: fp32 out. MODE 1: tf32(uint32) out.
// MODE 2: 3xTF32 compute, hi/lo-interleaved gmem out (g_DHL layout).
// Block 128x128, 256 threads (8 warps 2x4), warp tile 64x32, BK=16.
// X3 smem: SEPARATE hi/lo planes (conflict-free stores AND loads).
// A plane stride 137 (9*la3+l4 distinct), B plane stride 136 (8*la3+l4).
// ---------------------------------------------------------------------------
template<int MODE>
__global__ __launch_bounds__(256) void gemm_tc(const float* __restrict__ A,
                                               const float* __restrict__ W,
                                               const float* __restrict__ bias,
                                               void* __restrict__ Cout) {
    const bool X3 = (MODE == 2);
    const int AWS = 137, BWS = 136;
    const int ALO = 16 * AWS, BLO = 16 * BWS;   // lo-plane offsets
    __shared__ uint32_t As[(MODE == 2 ? 2 : 1) * 16 * 137];
    __shared__ uint32_t Bs[(MODE == 2 ? 2 : 1) * 16 * 136];
    int tid = threadIdx.x, lane = tid & 31, w = tid >> 5;
    int la3 = lane & 3, l4 = lane >> 2;
    int wm = (w & 1) * 64, wn = (w >> 1) * 32;
    int row0 = blockIdx.y * 128, col0 = blockIdx.x * 128;

    float acc[4][4][4] = {};

    for (int k0 = 0; k0 < HH; k0 += 16) {
        __syncthreads();
        #pragma unroll
        for (int i = 0; i < 2; i++) {           // A tile 128m x 16k -> As[k][m]
            int f = tid + i * 256;
            int r = f >> 2, cg = (f & 3) * 4;
            float4 v = *(const float4*)&A[(size_t)(row0 + r) * HH + k0 + cg];
            float vv[4] = {v.x, v.y, v.z, v.w};
            #pragma unroll
            for (int j = 0; j < 4; j++) {
                if (X3) {
                    uint32_t hh, ll; tf32split(vv[j], hh, ll);
                    As[(cg + j) * AWS + r]       = hh;
                    As[ALO + (cg + j) * AWS + r] = ll;
                } else {
                    As[(cg + j) * AWS + r] = f2tf32(vv[j]);
                }
            }
        }
        #pragma unroll
        for (int i = 0; i < 2; i++) {           // B tile 16k x 128n -> Bs[k][n]
            int f = tid + i * 256;
            int r = f >> 5, cg = (f & 31) * 4;
            float4 v = *(const float4*)&W[(size_t)(k0 + r) * HH + col0 + cg];
            float vv[4] = {v.x, v.y, v.z, v.w};
            #pragma unroll
            for (int j = 0; j < 4; j++) {
                if (X3) {
                    uint32_t hh, ll; tf32split(vv[j], hh, ll);
                    Bs[r * BWS + cg + j]       = hh;
                    Bs[BLO + r * BWS + cg + j] = ll;
                } else {
                    Bs[r * BWS + cg + j] = f2tf32(vv[j]);
                }
            }
        }
        __syncthreads();

        #pragma unroll
        for (int kk = 0; kk < 16; kk += 8) {
            int ra = (kk + la3) * AWS, rb = (kk + 4 + la3) * AWS;
            int rc = (kk + la3) * BWS, rd = (kk + 4 + la3) * BWS;
            if (X3) {
                uint32_t bh[4][2], bl[4][2];
                #pragma unroll
                for (int nt = 0; nt < 4; nt++) {
                    int n = wn + nt * 8 + l4;
                    bh[nt][0] = Bs[rc + n];       bh[nt][1] = Bs[rd + n];
                    bl[nt][0] = Bs[BLO + rc + n]; bl[nt][1] = Bs[BLO + rd + n];
                }
                #pragma unroll
                for (int mt = 0; mt < 4; mt++) {
                    int m = wm + mt * 16 + l4;
                    uint32_t h0 = As[ra + m],       h1 = As[ra + m + 8];
                    uint32_t h2 = As[rb + m],       h3 = As[rb + m + 8];
                    uint32_t l0 = As[ALO + ra + m], l1 = As[ALO + ra + m + 8];
                    uint32_t l2 = As[ALO + rb + m], l3 = As[ALO + rb + m + 8];
                    #pragma unroll
                    for (int nt = 0; nt < 4; nt++) {
                        mma8(acc[mt][nt], h0, h1, h2, h3, bh[nt][0], bh[nt][1]);
                        mma8(acc[mt][nt], h0, h1, h2, h3, bl[nt][0], bl[nt][1]);
                        mma8(acc[mt][nt], l0, l1, l2, l3, bh[nt][0], bh[nt][1]);
                    }
                }
            } else {
                uint32_t bf[4][2];
                #pragma unroll
                for (int nt = 0; nt < 4; nt++) {
                    int n = wn + nt * 8 + l4;
                    bf[nt][0] = Bs[rc + n];
                    bf[nt][1] = Bs[rd + n];
                }
                #pragma unroll
                for (int mt = 0; mt < 4; mt++) {
                    int m = wm + mt * 16 + l4;
                    uint32_t a0 = As[ra + m], a1 = As[ra + m + 8];
                    uint32_t a2 = As[rb + m], a3 = As[rb + m + 8];
                    #pragma unroll
                    for (int nt = 0; nt < 4; nt++)
                        mma8(acc[mt][nt], a0, a1, a2, a3, bf[nt][0], bf[nt][1]);
                }
            }
        }
    }

    #pragma unroll
    for (int mt = 0; mt < 4; mt++) {
        int r = row0 + wm + mt * 16 + l4;
        #pragma unroll
        for (int nt = 0; nt < 4; nt++) {
            int cb = col0 + wn + nt * 8 + 2 * la3;
            float v0 = acc[mt][nt][0] + bias[cb];
            float v1 = acc[mt][nt][1] + bias[cb + 1];
            float v2 = acc[mt][nt][2] + bias[cb];
            float v3 = acc[mt][nt][3] + bias[cb + 1];
            if (MODE == 0) {
                float* C = (float*)Cout;
                C[(size_t)r       * HH + cb    ] = v0;
                C[(size_t)r       * HH + cb + 1] = v1;
                C[(size_t)(r + 8) * HH + cb    ] = v2;
                C[(size_t)(r + 8) * HH + cb + 1] = v3;
            } else if (MODE == 1) {
                uint32_t* C = (uint32_t*)Cout;
                *(uint2*)&C[(size_t)r       * HH + cb] = make_uint2(f2tf32(v0), f2tf32(v1));
                *(uint2*)&C[(size_t)(r + 8) * HH + cb] = make_uint2(f2tf32(v2), f2tf32(v3));
            } else {
                uint32_t* C = (uint32_t*)Cout;
                uint32_t h0,l0,h1,l1,h2,l2,h3,l3;
                tf32split(v0, h0, l0); tf32split(v1, h1, l1);
                tf32split(v2, h2, l2); tf32split(v3, h3, l3);
                *(uint4*)&C[(size_t)r       * 2048 + 2 * cb] = make_uint4(h0, l0, h1, l1);
                *(uint4*)&C[(size_t)(r + 8) * 2048 + 2 * cb] = make_uint4(h2, l2, h3, l3);
            }
        }
    }
}

// ---------------------------------------------------------------------------
// g_Vt [B*S, H] tf32 -> g_VtP [(b,h,d), key-permuted] so PV b-fragments are
// single LDS.64: pos(s) = 8*(s>>3) + 2*(s&3) + ((s>>2)&1).
// ---------------------------------------------------------------------------
__global__ __launch_bounds__(256) void v_transpose(const uint32_t* __restrict__ Vt,
                                                   uint32_t* __restrict__ VtP) {
    __shared__ uint32_t Vs[64][65];
    int k0 = blockIdx.x * 64;
    int bh = blockIdx.y;                 // b*NH + h
    int b = bh >> 4, h = bh & 15;
    int tid = threadIdx.x;
    #pragma unroll
    for (int i = 0; i < 16; i++) {
        int idx = tid + i * 256;
        int r = idx >> 6, d = idx & 63;
        Vs[r][d] = Vt[(size_t)(b * SS + k0 + r) * HH + h * 64 + d];
    }
    __syncthreads();
    #pragma unroll
    for (int i = 0; i < 16; i++) {
        int idx = tid + i * 256;
        int d = idx >> 6, pr = idx & 63;
        int g = pr >> 3, rem = pr & 7;
        int r = g * 8 + (rem & 1) * 4 + (rem >> 1);
        VtP[(size_t)(bh * 64 + d) * SS + k0 + pr] = Vs[r][d];
    }
}

// ---------------------------------------------------------------------------
// Fused anti-causal gaussian attention (QK 3xTF32, PV tf32). Zero cvt inside.
// R4 skeleton: K-tile 64, 8 nt chains, 2 syncthreads + 1 syncwarp per tile.
// Inputs pre-split (g_DHL) / pre-permuted (g_VtP): fill = pure cp.async copy.
// Smem (u32): DkHL[64][136]=8704, Vp[64][72]=4608, Ps[64][72]=4608 -> 70.0KB.
// All strides === 8 (mod 32): conflict-free LDS.64 per half-warp.
// ---------------------------------------------------------------------------
__global__ __launch_bounds__(128, 3) void attn_tc(const uint32_t* __restrict__ DH,
                                                  const uint32_t* __restrict__ VtP,
                                                  float* __restrict__ C) {
    extern __shared__ uint32_t sm[];
    const int DK0 = 0;                 // [64][136]
    const int VT0 = 64 * 136;          // [64][72]
    const int PS0 = VT0 + 64 * 72;     // [64][72]

    int tid = threadIdx.x, lane = tid & 31, w = tid >> 5;
    int la3 = lane & 3, l4 = lane >> 2;
    int q0 = blockIdx.x * 64, h = blockIdx.y, b = blockIdx.z;
    const uint32_t* DHb = DH + (size_t)b * SS * 2048 + h * 128;
    const uint32_t* Vb  = VtP + (size_t)(b * NH + h) * HD * SS;
    int qrow = w * 16 + l4;

    uint32_t smb = smem_u32(sm);
    uint32_t dkb = smb + DK0 * 4;
    uint32_t vtb = smb + VT0 * 4;

    // Q-side fragments: pre-split hi/lo, loaded once (loop-invariant)
    uint32_t aH[8][4], aL[8][4];
    {
        const uint32_t* r0 = DHb + (size_t)(q0 + qrow) * 2048;
        const uint32_t* r8 = r0 + (size_t)8 * 2048;
        #pragma unroll
        for (int kk8 = 0; kk8 < 8; kk8++) {
            uint2 A0 = *(const uint2*)&r0[2 * (kk8 * 8 + la3)];
            uint2 A1 = *(const uint2*)&r8[2 * (kk8 * 8 + la3)];
            uint2 A2 = *(const uint2*)&r0[2 * (kk8 * 8 + 4 + la3)];
            uint2 A3 = *(const uint2*)&r8[2 * (kk8 * 8 + 4 + la3)];
            aH[kk8][0] = A0.x; aL[kk8][0] = A0.y;
            aH[kk8][1] = A1.x; aL[kk8][1] = A1.y;
            aH[kk8][2] = A2.x; aL[kk8][2] = A2.y;
            aH[kk8][3] = A3.x; aL[kk8][3] = A3.y;
        }
    }

    // P store positions (permuted key order, precomputed)
    int r8a = 2 * la3, r8b = 2 * la3 + 1;
    int pA = 2 * (r8a & 3) + ((r8a >> 2) & 1);
    int pB = 2 * (r8b & 3) + ((r8b >> 2) & 1);

    float ctx[8][4] = {};
    int nT = (SS - q0) / 64;

    for (int t = 0; t < nT; t++) {
        int k0 = q0 + t * 64;
        __syncthreads();                       // prior tile smem reads done
        // Fill DkHL (64 rows x 512B) + Vp (64 d-rows x 256B) via cp.async
        #pragma unroll
        for (int i = 0; i < 16; i++) {
            int idx = tid + i * 128;
            int r = idx >> 5, j = idx & 31;
            cp16(dkb + (r * 136 + 4 * j) * 4, DHb + (size_t)(k0 + r) * 2048 + 4 * j);
        }
        #pragma unroll
        for (int i = 0; i < 8; i++) {
            int idx = tid + i * 128;
            int d = idx >> 4, j = idx & 15;
            cp16(vtb + (d * 72 + 4 * j) * 4, Vb + (size_t)d * SS + k0 + 4 * j);
        }
        cp_commit();
        cp_wait<0>();
        __syncthreads();

        const uint32_t* Dk = sm + DK0;         // [64][136]
        const uint32_t* Vp = sm + VT0;         // [64][72]
        uint32_t* Pw = sm + PS0;               // [64][72]

        // ---- QK: S[16q x 64k] per warp, 3xTF32 ----
        float s4[8][4] = {};
        #pragma unroll
        for (int kk8 = 0; kk8 < 8; kk8++) {
            #pragma unroll
            for (int nt = 0; nt < 8; nt++) {
                const uint32_t* br = Dk + (nt * 8 + l4) * 136;
                uint2 p0 = *(const uint2*)&br[2 * (kk8 * 8 + la3)];
                uint2 p1 = *(const uint2*)&br[2 * (kk8 * 8 + 4 + la3)];
                mma8(s4[nt], aH[kk8][0], aH[kk8][1], aH[kk8][2], aH[kk8][3], p0.x, p1.x);
                mma8(s4[nt], aH[kk8][0], aH[kk8][1], aH[kk8][2], aH[kk8][3], p0.y, p1.y);
                mma8(s4[nt], aL[kk8][0], aL[kk8][1], aL[kk8][2], aL[kk8][3], p0.x, p1.x);
            }
        }

        // ---- mask (k > q strictly) + exp -> Ps (permuted cols, tf32) ----
        #pragma unroll
        for (int nt = 0; nt < 8; nt++) {
            int kgA = k0 + nt * 8 + r8a;
            float p0 = (kgA     > q0 + qrow)     ? __expf(-0.5f * s4[nt][0]) : 0.0f;
            float p1 = (kgA + 1 > q0 + qrow)     ? __expf(-0.5f * s4[nt][1]) : 0.0f;
            float p2 = (kgA     > q0 + qrow + 8) ? __expf(-0.5f * s4[nt][2]) : 0.0f;
            float p3 = (kgA + 1 > q0 + qrow + 8) ? __expf(-0.5f * s4[nt][3]) : 0.0f;
            Pw[qrow * 72 + nt * 8 + pA]       = f2tf32(p0);
            Pw[qrow * 72 + nt * 8 + pB]       = f2tf32(p1);
            Pw[(qrow + 8) * 72 + nt * 8 + pA] = f2tf32(p2);
            Pw[(qrow + 8) * 72 + nt * 8 + pB] = f2tf32(p3);
        }
        __syncwarp();   // Pw rows are warp-private

        // ---- PV: ctx[16q x 64d] += P @ V over 64 keys (all LDS.64) ----
        #pragma unroll
        for (int kt = 0; kt < 8; kt++) {
            int kk = kt * 8;
            uint2 ua = *(const uint2*)&Pw[qrow * 72 + kk + 2 * la3];
            uint2 ub = *(const uint2*)&Pw[(qrow + 8) * 72 + kk + 2 * la3];
            #pragma unroll
            for (int nt = 0; nt < 8; nt++) {
                uint2 vb2 = *(const uint2*)&Vp[(nt * 8 + l4) * 72 + kk + 2 * la3];
                mma8(ctx[nt], ua.x, ub.x, ua.y, ub.y, vb2.x, vb2.y);
            }
        }
    }

    // Store ctx in merged [B,S,H] layout
    float* Cb = C + (size_t)b * SS * HH + h * HD;
    #pragma unroll
    for (int nt = 0; nt < 8; nt++) {
        int r = q0 + qrow;
        int c = nt * 8 + 2 * la3;
        Cb[(size_t)r       * HH + c    ] = ctx[nt][0];
        Cb[(size_t)r       * HH + c + 1] = ctx[nt][1];
        Cb[(size_t)(r + 8) * HH + c    ] = ctx[nt][2];
        Cb[(size_t)(r + 8) * HH + c + 1] = ctx[nt][3];
    }
}

static const int ATTN_SMEM = (64 * 136 + 64 * 72 + 64 * 72) * 4;   // 71680 B

extern "C" void kernel_launch(void* const* d_in, const int* in_sizes, int n_in,
                              void* d_out, int out_size) {
    const float* x  = (const float*)d_in[0];
    const float* Wq = (const float*)d_in[1];
    const float* bq = (const float*)d_in[2];
    const float* Wk = (const float*)d_in[3];
    const float* bk = (const float*)d_in[4];
    const float* Wv = (const float*)d_in[5];
    const float* bv = (const float*)d_in[6];
    const float* Wo = (const float*)d_in[7];
    const float* bo = (const float*)d_in[8];
    float* out = (float*)d_out;

    float *pWd, *pbd, *pC;
    uint32_t *pDHL, *pVt, *pVtP;
    cudaGetSymbolAddress((void**)&pWd,  g_Wd);
    cudaGetSymbolAddress((void**)&pbd,  g_bd);
    cudaGetSymbolAddress((void**)&pDHL, g_DHL);
    cudaGetSymbolAddress((void**)&pVt,  g_Vt);
    cudaGetSymbolAddress((void**)&pVtP, g_VtP);
    cudaGetSymbolAddress((void**)&pC,   g_C);

    static bool attr_set = false;
    if (!attr_set) {
        cudaFuncSetAttribute(attn_tc, cudaFuncAttributeMaxDynamicSharedMemorySize, ATTN_SMEM);
        attr_set = true;
    }

    // 1. Wd = Wq - Wk, bd = bq - bk
    sub_wb_kernel<<<(HH*HH + 255) / 256, 256>>>(Wq, Wk, bq, bk);

    // 2. D = x @ Wd + bd (3xTF32, pre-split out) ; V = x @ Wv + bv (tf32 out)
    dim3 ggrid(HH / 128, MM / 128);
    gemm_tc<2><<<ggrid, 256>>>(x, pWd, pbd, pDHL);
    gemm_tc<1><<<ggrid, 256>>>(x, Wv, bv, pVt);

    // 3. V transpose+permute for LDS.64 b-fragments
    v_transpose<<<dim3(SS / 64, BB * NH), 256>>>(pVt, pVtP);

    // 4. fused attention -> ctx in [B,S,H] layout
    dim3 agrid(SS / 64, NH, BB);
    attn_tc<<<agrid, 128, ATTN_SMEM>>>(pDHL, pVtP, pC);

    // 5. out = ctx @ Wo + bo (tf32)
    gemm_tc<0><<<ggrid, 256>>>(pC, Wo, bo, out);
}

// round 7
// speedup vs baseline: 1.5520x; 1.4877x over previous
#include <cuda_runtime.h>
#include <cuda_bf16.h>
#include <cstdint>

#define BB 2
#define SS 2048
#define HH 1024
#define NH 16
#define HD 64
#define MM (BB*SS)   // 4096 rows

// Scratch (allocation is forbidden; use __device__ globals)
__device__ float    g_Wd[HH*HH];
__device__ float    g_bd[HH];
__device__ uint32_t g_DHL[(size_t)MM*HH];         // D, bf16 hi/lo pair-interleaved:
                                                  // row r, dim-pair p of head h at [r*1024 + h*64 + 2p](hi),[+1](lo)
__device__ uint32_t g_Vt[(size_t)MM*HH];          // V, tf32, row-major
__device__ uint32_t g_VtP[(size_t)BB*NH*HD*SS];   // V^T, permuted keys, per (b,h)
__device__ float    g_C[(size_t)MM*HH];

__device__ __forceinline__ uint32_t f2tf32(float x) {
    uint32_t r;
    asm("cvt.rna.tf32.f32 %0, %1;" : "=r"(r) : "f"(x));
    return r;
}
// pack bf16(x0) into low 16 bits, bf16(x1) into high 16 bits
__device__ __forceinline__ uint32_t bfpack(float x0, float x1) {
    __nv_bfloat162 t;
    t.x = __float2bfloat16_rn(x0);
    t.y = __float2bfloat16_rn(x1);
    return *(uint32_t*)&t;
}
// split (x0,x1) into packed hi-pair and lo-pair (x = hi + lo + O(2^-18 x))
__device__ __forceinline__ void bfsplit2(float x0, float x1, uint32_t& hi, uint32_t& lo) {
    __nv_bfloat16 h0 = __float2bfloat16_rn(x0), h1 = __float2bfloat16_rn(x1);
    float r0 = x0 - __bfloat162float(h0), r1 = x1 - __bfloat162float(h1);
    __nv_bfloat162 th; th.x = h0; th.y = h1;
    hi = *(uint32_t*)&th;
    lo = bfpack(r0, r1);
}
// tf32 m16n8k8
__device__ __forceinline__ void mma8(float* c,
                                     uint32_t a0, uint32_t a1, uint32_t a2, uint32_t a3,
                                     uint32_t b0, uint32_t b1) {
    asm volatile(
        "mma.sync.aligned.m16n8k8.row.col.f32.tf32.tf32.f32 "
        "{%0,%1,%2,%3}, {%4,%5,%6,%7}, {%8,%9}, {%0,%1,%2,%3};"
        : "+f"(c[0]), "+f"(c[1]), "+f"(c[2]), "+f"(c[3])
        : "r"(a0), "r"(a1), "r"(a2), "r"(a3), "r"(b0), "r"(b1));
}
// bf16 m16n8k16
__device__ __forceinline__ void mma16(float* c,
                                      uint32_t a0, uint32_t a1, uint32_t a2, uint32_t a3,
                                      uint32_t b0, uint32_t b1) {
    asm volatile(
        "mma.sync.aligned.m16n8k16.row.col.f32.bf16.bf16.f32 "
        "{%0,%1,%2,%3}, {%4,%5,%6,%7}, {%8,%9}, {%0,%1,%2,%3};"
        : "+f"(c[0]), "+f"(c[1]), "+f"(c[2]), "+f"(c[3])
        : "r"(a0), "r"(a1), "r"(a2), "r"(a3), "r"(b0), "r"(b1));
}
__device__ __forceinline__ uint32_t smem_u32(const void* p) {
    uint32_t a;
    asm("{ .reg .u64 t; cvta.to.shared.u64 t, %1; cvt.u32.u64 %0, t; }" : "=r"(a) : "l"(p));
    return a;
}
__device__ __forceinline__ void cp16(uint32_t dst, const void* src) {
    asm volatile("cp.async.ca.shared.global [%0], [%1], 16;" :: "r"(dst), "l"(src));
}
__device__ __forceinline__ void cp_commit() { asm volatile("cp.async.commit_group;"); }
template<int N> __device__ __forceinline__ void cp_wait() {
    asm volatile("cp.async.wait_group %0;" :: "n"(N));
}

// Wd = Wq - Wk, bd = bq - bk
__global__ void sub_wb_kernel(const float* __restrict__ Wq, const float* __restrict__ Wk,
                              const float* __restrict__ bq, const float* __restrict__ bk) {
    int i = blockIdx.x * blockDim.x + threadIdx.x;
    if (i < HH*HH) g_Wd[i] = Wq[i] - Wk[i];
    if (i < HH)    g_bd[i] = bq[i] - bk[i];
}

// ---------------------------------------------------------------------------
// Plain tf32 GEMM: C = A @ W + bias.  MODE 0: fp32 out. MODE 1: tf32 out.
// (unchanged proven R6 path)
// ---------------------------------------------------------------------------
template<int MODE>
__global__ __launch_bounds__(256) void gemm_tc(const float* __restrict__ A,
                                               const float* __restrict__ W,
                                               const float* __restrict__ bias,
                                               void* __restrict__ Cout) {
    const int AWS = 137, BWS = 136;
    __shared__ uint32_t As[16 * 137];
    __shared__ uint32_t Bs[16 * 136];
    int tid = threadIdx.x, lane = tid & 31, w = tid >> 5;
    int la3 = lane & 3, l4 = lane >> 2;
    int wm = (w & 1) * 64, wn = (w >> 1) * 32;
    int row0 = blockIdx.y * 128, col0 = blockIdx.x * 128;

    float acc[4][4][4] = {};

    for (int k0 = 0; k0 < HH; k0 += 16) {
        __syncthreads();
        #pragma unroll
        for (int i = 0; i < 2; i++) {           // A tile 128m x 16k -> As[k][m]
            int f = tid + i * 256;
            int r = f >> 2, cg = (f & 3) * 4;
            float4 v = *(const float4*)&A[(size_t)(row0 + r) * HH + k0 + cg];
            As[(cg + 0) * AWS + r] = f2tf32(v.x);
            As[(cg + 1) * AWS + r] = f2tf32(v.y);
            As[(cg + 2) * AWS + r] = f2tf32(v.z);
            As[(cg + 3) * AWS + r] = f2tf32(v.w);
        }
        #pragma unroll
        for (int i = 0; i < 2; i++) {           // B tile 16k x 128n -> Bs[k][n]
            int f = tid + i * 256;
            int r = f >> 5, cg = (f & 31) * 4;
            float4 v = *(const float4*)&W[(size_t)(k0 + r) * HH + col0 + cg];
            Bs[r * BWS + cg + 0] = f2tf32(v.x);
            Bs[r * BWS + cg + 1] = f2tf32(v.y);
            Bs[r * BWS + cg + 2] = f2tf32(v.z);
            Bs[r * BWS + cg + 3] = f2tf32(v.w);
        }
        __syncthreads();

        #pragma unroll
        for (int kk = 0; kk < 16; kk += 8) {
            int ra = (kk + la3) * AWS, rb = (kk + 4 + la3) * AWS;
            int rc = (kk + la3) * BWS, rd = (kk + 4 + la3) * BWS;
            uint32_t bf[4][2];
            #pragma unroll
            for (int nt = 0; nt < 4; nt++) {
                int n = wn + nt * 8 + l4;
                bf[nt][0] = Bs[rc + n];
                bf[nt][1] = Bs[rd + n];
            }
            #pragma unroll
            for (int mt = 0; mt < 4; mt++) {
                int m = wm + mt * 16 + l4;
                uint32_t a0 = As[ra + m], a1 = As[ra + m + 8];
                uint32_t a2 = As[rb + m], a3 = As[rb + m + 8];
                #pragma unroll
                for (int nt = 0; nt < 4; nt++)
                    mma8(acc[mt][nt], a0, a1, a2, a3, bf[nt][0], bf[nt][1]);
            }
        }
    }

    #pragma unroll
    for (int mt = 0; mt < 4; mt++) {
        int r = row0 + wm + mt * 16 + l4;
        #pragma unroll
        for (int nt = 0; nt < 4; nt++) {
            int cb = col0 + wn + nt * 8 + 2 * la3;
            float v0 = acc[mt][nt][0] + bias[cb];
            float v1 = acc[mt][nt][1] + bias[cb + 1];
            float v2 = acc[mt][nt][2] + bias[cb];
            float v3 = acc[mt][nt][3] + bias[cb + 1];
            if (MODE == 0) {
                float* C = (float*)Cout;
                C[(size_t)r       * HH + cb    ] = v0;
                C[(size_t)r       * HH + cb + 1] = v1;
                C[(size_t)(r + 8) * HH + cb    ] = v2;
                C[(size_t)(r + 8) * HH + cb + 1] = v3;
            } else {
                uint32_t* C = (uint32_t*)Cout;
                *(uint2*)&C[(size_t)r       * HH + cb] = make_uint2(f2tf32(v0), f2tf32(v1));
                *(uint2*)&C[(size_t)(r + 8) * HH + cb] = make_uint2(f2tf32(v2), f2tf32(v3));
            }
        }
    }
}

// ---------------------------------------------------------------------------
// D = x @ Wd + bd in 3xBF16 (m16n8k16), output bf16 hi/lo pair-interleaved.
// Block 128x128, 256 threads (8 warps 2x4), warp tile 64x32, BK=32.
// Smem planes: Ah/Al [pair][m] stride 134, Bh/Bl [pair][n] stride 132.
// ---------------------------------------------------------------------------
__global__ __launch_bounds__(256) void gemm_bf3(const float* __restrict__ A,
                                                const float* __restrict__ W,
                                                const float* __restrict__ bias,
                                                uint32_t* __restrict__ Cout) {
    const int AST = 134, BST = 132;
    __shared__ uint32_t Ah[16 * 134], Al[16 * 134];
    __shared__ uint32_t Bh[16 * 132], Bl[16 * 132];
    int tid = threadIdx.x, lane = tid & 31, w = tid >> 5;
    int la3 = lane & 3, l4 = lane >> 2;
    int wm = (w & 1) * 64, wn = (w >> 1) * 32;
    int row0 = blockIdx.y * 128, col0 = blockIdx.x * 128;

    float acc[4][4][4] = {};

    for (int k0 = 0; k0 < HH; k0 += 32) {
        __syncthreads();
        // A tile: 128 rows x 32 k (1024 float4, 4/thread) -> pair planes
        #pragma unroll
        for (int i = 0; i < 4; i++) {
            int f = tid + i * 256;
            int r = f >> 3, c4 = (f & 7) * 4;     // k-offset c4, pairs c4/2, c4/2+1
            float4 v = *(const float4*)&A[(size_t)(row0 + r) * HH + k0 + c4];
            int p = c4 >> 1;
            uint32_t h, l;
            bfsplit2(v.x, v.y, h, l);
            Ah[p * AST + r] = h;  Al[p * AST + r] = l;
            bfsplit2(v.z, v.w, h, l);
            Ah[(p + 1) * AST + r] = h;  Al[(p + 1) * AST + r] = l;
        }
        // B tile: 16 k-pairs x 128 n (512 tasks of 4 n, 2/thread)
        #pragma unroll
        for (int i = 0; i < 2; i++) {
            int f = tid + i * 256;
            int p = f >> 5, j = f & 31;
            const float* w0 = &W[(size_t)(k0 + 2 * p) * HH + col0 + 4 * j];
            float4 u0 = *(const float4*)w0;
            float4 u1 = *(const float4*)(w0 + HH);
            uint32_t hh[4], ll[4];
            bfsplit2(u0.x, u1.x, hh[0], ll[0]);
            bfsplit2(u0.y, u1.y, hh[1], ll[1]);
            bfsplit2(u0.z, u1.z, hh[2], ll[2]);
            bfsplit2(u0.w, u1.w, hh[3], ll[3]);
            *(uint4*)&Bh[p * BST + 4 * j] = make_uint4(hh[0], hh[1], hh[2], hh[3]);
            *(uint4*)&Bl[p * BST + 4 * j] = make_uint4(ll[0], ll[1], ll[2], ll[3]);
        }
        __syncthreads();

        #pragma unroll
        for (int ks = 0; ks < 2; ks++) {          // two k16 steps
            int pb = ks * 8;
            int ra = (pb + la3) * AST, rb = (pb + 4 + la3) * AST;
            int rc = (pb + la3) * BST, rd = (pb + 4 + la3) * BST;
            uint32_t bh[4][2], bl[4][2];
            #pragma unroll
            for (int nt = 0; nt < 4; nt++) {
                int n = wn + nt * 8 + l4;
                bh[nt][0] = Bh[rc + n];  bh[nt][1] = Bh[rd + n];
                bl[nt][0] = Bl[rc + n];  bl[nt][1] = Bl[rd + n];
            }
            #pragma unroll
            for (int mt = 0; mt < 4; mt++) {
                int m = wm + mt * 16 + l4;
                uint32_t h0 = Ah[ra + m], h1 = Ah[ra + m + 8];
                uint32_t h2 = Ah[rb + m], h3 = Ah[rb + m + 8];
                uint32_t l0 = Al[ra + m], l1 = Al[ra + m + 8];
                uint32_t l2 = Al[rb + m], l3 = Al[rb + m + 8];
                #pragma unroll
                for (int nt = 0; nt < 4; nt++) {
                    mma16(acc[mt][nt], h0, h1, h2, h3, bh[nt][0], bh[nt][1]);
                    mma16(acc[mt][nt], h0, h1, h2, h3, bl[nt][0], bl[nt][1]);
                    mma16(acc[mt][nt], l0, l1, l2, l3, bh[nt][0], bh[nt][1]);
                }
            }
        }
    }

    // epilogue: fp32 acc + bias -> bf16 hi/lo packed pairs (cb is even)
    #pragma unroll
    for (int mt = 0; mt < 4; mt++) {
        int r = row0 + wm + mt * 16 + l4;
        #pragma unroll
        for (int nt = 0; nt < 4; nt++) {
            int cb = col0 + wn + nt * 8 + 2 * la3;
            float v0 = acc[mt][nt][0] + bias[cb];
            float v1 = acc[mt][nt][1] + bias[cb + 1];
            float v2 = acc[mt][nt][2] + bias[cb];
            float v3 = acc[mt][nt][3] + bias[cb + 1];
            uint32_t h, l;
            bfsplit2(v0, v1, h, l);
            *(uint2*)&Cout[(size_t)r * HH + cb] = make_uint2(h, l);
            bfsplit2(v2, v3, h, l);
            *(uint2*)&Cout[(size_t)(r + 8) * HH + cb] = make_uint2(h, l);
        }
    }
}

// ---------------------------------------------------------------------------
// g_Vt [B*S, H] tf32 -> g_VtP [(b,h,d), key-permuted] so PV b-fragments are
// single LDS.64: pos(s) = 8*(s>>3) + 2*(s&3) + ((s>>2)&1).
// ---------------------------------------------------------------------------
__global__ __launch_bounds__(256) void v_transpose(const uint32_t* __restrict__ Vt,
                                                   uint32_t* __restrict__ VtP) {
    __shared__ uint32_t Vs[64][65];
    int k0 = blockIdx.x * 64;
    int bh = blockIdx.y;                 // b*NH + h
    int b = bh >> 4, h = bh & 15;
    int tid = threadIdx.x;
    #pragma unroll
    for (int i = 0; i < 16; i++) {
        int idx = tid + i * 256;
        int r = idx >> 6, d = idx & 63;
        Vs[r][d] = Vt[(size_t)(b * SS + k0 + r) * HH + h * 64 + d];
    }
    __syncthreads();
    #pragma unroll
    for (int i = 0; i < 16; i++) {
        int idx = tid + i * 256;
        int d = idx >> 6, pr = idx & 63;
        int g = pr >> 3, rem = pr & 7;
        int r = g * 8 + (rem & 1) * 4 + (rem >> 1);
        VtP[(size_t)(bh * 64 + d) * SS + k0 + pr] = Vs[r][d];
    }
}

// ---------------------------------------------------------------------------
// Fused anti-causal gaussian attention. QK 3xBF16 (m16n8k16), PV tf32.
// K-tile 64, software-pipelined single-buffer fills:
//   Dk(t+1) prefetch overlaps mask+PV(t); V(t+1) prefetch overlaps QK(t+1).
// Smem (u32): Dk[64][72], Vp[64][72], Ps[64][72] = 54KB -> 4 CTAs/SM.
// ---------------------------------------------------------------------------
__global__ __launch_bounds__(128, 4) void attn_tc(const uint32_t* __restrict__ DH,
                                                  const uint32_t* __restrict__ VtP,
                                                  float* __restrict__ C) {
    extern __shared__ uint32_t sm[];
    const int DK0 = 0;                 // [64][72] bf16 hi/lo pair-interleaved
    const int VT0 = 64 * 72;           // [64][72] tf32, permuted keys
    const int PS0 = VT0 + 64 * 72;     // [64][72] tf32, permuted keys

    int tid = threadIdx.x, lane = tid & 31, w = tid >> 5;
    int la3 = lane & 3, l4 = lane >> 2;
    int q0 = blockIdx.x * 64, h = blockIdx.y, b = blockIdx.z;
    const uint32_t* DHb = DH + (size_t)b * SS * HH + h * 64;
    const uint32_t* Vb  = VtP + (size_t)(b * NH + h) * HD * SS;
    int qrow = w * 16 + l4;

    uint32_t smb = smem_u32(sm);
    uint32_t dkb = smb + DK0 * 4;
    uint32_t vtb = smb + VT0 * 4;

    // Q-side fragments: packed bf16 hi/lo, loaded once (loop-invariant)
    uint32_t aH[4][4], aL[4][4];
    {
        const uint32_t* r0 = DHb + (size_t)(q0 + qrow) * HH;
        const uint32_t* r8 = r0 + (size_t)8 * HH;
        #pragma unroll
        for (int K = 0; K < 4; K++) {
            uint2 A0 = *(const uint2*)&r0[2 * (K * 8 + la3)];
            uint2 A1 = *(const uint2*)&r8[2 * (K * 8 + la3)];
            uint2 A2 = *(const uint2*)&r0[2 * (K * 8 + 4 + la3)];
            uint2 A3 = *(const uint2*)&r8[2 * (K * 8 + 4 + la3)];
            aH[K][0] = A0.x; aL[K][0] = A0.y;
            aH[K][1] = A1.x; aL[K][1] = A1.y;
            aH[K][2] = A2.x; aL[K][2] = A2.y;
            aH[K][3] = A3.x; aL[K][3] = A3.y;
        }
    }

    // P store positions (permuted key order, precomputed)
    int r8a = 2 * la3, r8b = 2 * la3 + 1;
    int pA = 2 * (r8a & 3) + ((r8a >> 2) & 1);
    int pB = 2 * (r8b & 3) + ((r8b >> 2) & 1);

    float ctx[8][4] = {};
    int nT = (SS - q0) / 64;

    // Dk fill: 64 rows x 64 u32 (256B) = 1024 cp16 -> 8/thread
    #define FILL_DK(T) do {                                                      \
        int k0t = q0 + (T) * 64;                                                 \
        _Pragma("unroll")                                                        \
        for (int i = 0; i < 8; i++) {                                            \
            int idx = tid + i * 128;                                             \
            int r = idx >> 4, j = idx & 15;                                      \
            cp16(dkb + (r * 72 + 4 * j) * 4,                                     \
                 DHb + (size_t)(k0t + r) * HH + 4 * j);                          \
        }                                                                        \
    } while (0)
    // V fill: 64 d-rows x 64 u32 = 1024 cp16 -> 8/thread
    #define FILL_V(T) do {                                                       \
        int k0t = q0 + (T) * 64;                                                 \
        _Pragma("unroll")                                                        \
        for (int i = 0; i < 8; i++) {                                            \
            int idx = tid + i * 128;                                             \
            int d = idx >> 4, j = idx & 15;                                      \
            cp16(vtb + (d * 72 + 4 * j) * 4,                                     \
                 Vb + (size_t)d * SS + k0t + 4 * j);                             \
        }                                                                        \
    } while (0)

    FILL_DK(0); cp_commit();
    FILL_V(0);  cp_commit();

    for (int t = 0; t < nT; t++) {
        int k0 = q0 + t * 64;
        cp_wait<1>();          // Dk(t) resident (V(t) may still be in flight)
        __syncthreads();

        const uint32_t* Dk = sm + DK0;
        const uint32_t* Vp = sm + VT0;
        uint32_t* Pw = sm + PS0;

        // ---- QK: S[16q x 64k] per warp, 3xBF16 over d=64 ----
        float s4[8][4] = {};
        #pragma unroll
        for (int K = 0; K < 4; K++) {
            #pragma unroll
            for (int nt = 0; nt < 8; nt++) {
                const uint32_t* br = Dk + (nt * 8 + l4) * 72;
                uint2 P0 = *(const uint2*)&br[2 * (K * 8 + la3)];
                uint2 P1 = *(const uint2*)&br[2 * (K * 8 + 4 + la3)];
                mma16(s4[nt], aH[K][0], aH[K][1], aH[K][2], aH[K][3], P0.x, P1.x);
                mma16(s4[nt], aH[K][0], aH[K][1], aH[K][2], aH[K][3], P0.y, P1.y);
                mma16(s4[nt], aL[K][0], aL[K][1], aL[K][2], aL[K][3], P0.x, P1.x);
            }
        }

        __syncthreads();                       // all warps done reading Dk
        if (t + 1 < nT) FILL_DK(t + 1);        // overlaps mask + PV
        cp_commit();

        // ---- mask (k > q strictly) + exp -> Ps (permuted cols, tf32) ----
        #pragma unroll
        for (int nt = 0; nt < 8; nt++) {
            int kgA = k0 + nt * 8 + r8a;
            float p0 = (kgA     > q0 + qrow)     ? __expf(-0.5f * s4[nt][0]) : 0.0f;
            float p1 = (kgA + 1 > q0 + qrow)     ? __expf(-0.5f * s4[nt][1]) : 0.0f;
            float p2 = (kgA     > q0 + qrow + 8) ? __expf(-0.5f * s4[nt][2]) : 0.0f;
            float p3 = (kgA + 1 > q0 + qrow + 8) ? __expf(-0.5f * s4[nt][3]) : 0.0f;
            Pw[qrow * 72 + nt * 8 + pA]       = f2tf32(p0);
            Pw[qrow * 72 + nt * 8 + pB]       = f2tf32(p1);
            Pw[(qrow + 8) * 72 + nt * 8 + pA] = f2tf32(p2);
            Pw[(qrow + 8) * 72 + nt * 8 + pB] = f2tf32(p3);
        }
        __syncwarp();   // Pw rows are warp-private

        cp_wait<1>();          // V(t) resident (Dk(t+1) may still be in flight)
        __syncthreads();

        // ---- PV: ctx[16q x 64d] += P @ V over 64 keys (all LDS.64, tf32) ----
        #pragma unroll
        for (int kt = 0; kt < 8; kt++) {
            int kk = kt * 8;
            uint2 ua = *(const uint2*)&Pw[qrow * 72 + kk + 2 * la3];
            uint2 ub = *(const uint2*)&Pw[(qrow + 8) * 72 + kk + 2 * la3];
            #pragma unroll
            for (int nt = 0; nt < 8; nt++) {
                uint2 vb2 = *(const uint2*)&Vp[(nt * 8 + l4) * 72 + kk + 2 * la3];
                mma8(ctx[nt], ua.x, ub.x, ua.y, ub.y, vb2.x, vb2.y);
            }
        }

        __syncthreads();                       // all warps done reading Vp/Ps
        if (t + 1 < nT) FILL_V(t + 1);         // overlaps next QK
        cp_commit();
    }

    // Store ctx in merged [B,S,H] layout
    float* Cb = C + (size_t)b * SS * HH + h * HD;
    #pragma unroll
    for (int nt = 0; nt < 8; nt++) {
        int r = q0 + qrow;
        int c = nt * 8 + 2 * la3;
        Cb[(size_t)r       * HH + c    ] = ctx[nt][0];
        Cb[(size_t)r       * HH + c + 1] = ctx[nt][1];
        Cb[(size_t)(r + 8) * HH + c    ] = ctx[nt][2];
        Cb[(size_t)(r + 8) * HH + c + 1] = ctx[nt][3];
    }
    #undef FILL_DK
    #undef FILL_V
}

static const int ATTN_SMEM = (3 * 64 * 72) * 4;   // 55296 B

extern "C" void kernel_launch(void* const* d_in, const int* in_sizes, int n_in,
                              void* d_out, int out_size) {
    const float* x  = (const float*)d_in[0];
    const float* Wq = (const float*)d_in[1];
    const float* bq = (const float*)d_in[2];
    const float* Wk = (const float*)d_in[3];
    const float* bk = (const float*)d_in[4];
    const float* Wv = (const float*)d_in[5];
    const float* bv = (const float*)d_in[6];
    const float* Wo = (const float*)d_in[7];
    const float* bo = (const float*)d_in[8];
    float* out = (float*)d_out;

    float *pWd, *pbd, *pC;
    uint32_t *pDHL, *pVt, *pVtP;
    cudaGetSymbolAddress((void**)&pWd,  g_Wd);
    cudaGetSymbolAddress((void**)&pbd,  g_bd);
    cudaGetSymbolAddress((void**)&pDHL, g_DHL);
    cudaGetSymbolAddress((void**)&pVt,  g_Vt);
    cudaGetSymbolAddress((void**)&pVtP, g_VtP);
    cudaGetSymbolAddress((void**)&pC,   g_C);

    static bool attr_set = false;
    if (!attr_set) {
        cudaFuncSetAttribute(attn_tc, cudaFuncAttributeMaxDynamicSharedMemorySize, ATTN_SMEM);
        attr_set = true;
    }

    // 1. Wd = Wq - Wk, bd = bq - bk
    sub_wb_kernel<<<(HH*HH + 255) / 256, 256>>>(Wq, Wk, bq, bk);

    // 2. D = x @ Wd + bd (3xBF16, hi/lo out) ; V = x @ Wv + bv (tf32 out)
    dim3 ggrid(HH / 128, MM / 128);
    gemm_bf3<<<ggrid, 256>>>(x, pWd, pbd, pDHL);
    gemm_tc<1><<<ggrid, 256>>>(x, Wv, bv, pVt);

    // 3. V transpose+permute for LDS.64 b-fragments
    v_transpose<<<dim3(SS / 64, BB * NH), 256>>>(pVt, pVtP);

    // 4. fused attention -> ctx in [B,S,H] layout
    dim3 agrid(SS / 64, NH, BB);
    attn_tc<<<agrid, 128, ATTN_SMEM>>>(pDHL, pVtP, pC);

    // 5. out = ctx @ Wo + bo (tf32)
    gemm_tc<0><<<ggrid, 256>>>(pC, Wo, bo, out);
}

// round 8
// speedup vs baseline: 1.6084x; 1.0363x over previous
#include <cuda_runtime.h>
#include <cuda_bf16.h>
#include <cstdint>

#define BB 2
#define SS 2048
#define HH 1024
#define NH 16
#define HD 64
#define MM (BB*SS)   // 4096 rows

// Scratch (allocation is forbidden; use __device__ globals)
__device__ uint32_t g_xTF[(size_t)MM*HH];         // x as tf32
__device__ uint32_t g_xHL[(size_t)MM*HH];         // x as bf16 hi/lo pair-interleaved
__device__ uint32_t g_WdHL[(size_t)(HH/2)*2*HH];  // Wq-Wk, bf16 hi/lo: [512 k-pairs][2048]
__device__ uint32_t g_WvTF[(size_t)HH*HH];        // Wv as tf32
__device__ uint32_t g_WoTF[(size_t)HH*HH];        // Wo as tf32
__device__ float    g_bd[HH];
__device__ uint32_t g_DHL[(size_t)MM*HH];         // D, bf16 hi/lo pair-interleaved
__device__ uint32_t g_VtP[(size_t)BB*NH*HD*SS];   // V^T tf32, permuted keys, per (b,h)
__device__ uint32_t g_C[(size_t)MM*HH];           // ctx as tf32

__device__ __forceinline__ uint32_t f2tf32(float x) {
    uint32_t r;
    asm("cvt.rna.tf32.f32 %0, %1;" : "=r"(r) : "f"(x));
    return r;
}
__device__ __forceinline__ uint32_t bfpack(float x0, float x1) {
    __nv_bfloat162 t;
    t.x = __float2bfloat16_rn(x0);
    t.y = __float2bfloat16_rn(x1);
    return *(uint32_t*)&t;
}
__device__ __forceinline__ void bfsplit2(float x0, float x1, uint32_t& hi, uint32_t& lo) {
    __nv_bfloat16 h0 = __float2bfloat16_rn(x0), h1 = __float2bfloat16_rn(x1);
    float r0 = x0 - __bfloat162float(h0), r1 = x1 - __bfloat162float(h1);
    __nv_bfloat162 th; th.x = h0; th.y = h1;
    hi = *(uint32_t*)&th;
    lo = bfpack(r0, r1);
}
__device__ __forceinline__ void mma8(float* c,
                                     uint32_t a0, uint32_t a1, uint32_t a2, uint32_t a3,
                                     uint32_t b0, uint32_t b1) {
    asm volatile(
        "mma.sync.aligned.m16n8k8.row.col.f32.tf32.tf32.f32 "
        "{%0,%1,%2,%3}, {%4,%5,%6,%7}, {%8,%9}, {%0,%1,%2,%3};"
        : "+f"(c[0]), "+f"(c[1]), "+f"(c[2]), "+f"(c[3])
        : "r"(a0), "r"(a1), "r"(a2), "r"(a3), "r"(b0), "r"(b1));
}
__device__ __forceinline__ void mma16(float* c,
                                      uint32_t a0, uint32_t a1, uint32_t a2, uint32_t a3,
                                      uint32_t b0, uint32_t b1) {
    asm volatile(
        "mma.sync.aligned.m16n8k16.row.col.f32.bf16.bf16.f32 "
        "{%0,%1,%2,%3}, {%4,%5,%6,%7}, {%8,%9}, {%0,%1,%2,%3};"
        : "+f"(c[0]), "+f"(c[1]), "+f"(c[2]), "+f"(c[3])
        : "r"(a0), "r"(a1), "r"(a2), "r"(a3), "r"(b0), "r"(b1));
}
__device__ __forceinline__ uint32_t smem_u32(const void* p) {
    uint32_t a;
    asm("{ .reg .u64 t; cvta.to.shared.u64 t, %1; cvt.u32.u64 %0, t; }" : "=r"(a) : "l"(p));
    return a;
}
__device__ __forceinline__ void cp16(uint32_t dst, const void* src) {
    asm volatile("cp.async.ca.shared.global [%0], [%1], 16;" :: "r"(dst), "l"(src));
}
__device__ __forceinline__ void cp_commit() { asm volatile("cp.async.commit_group;"); }
template<int N> __device__ __forceinline__ void cp_wait() {
    asm volatile("cp.async.wait_group %0;" :: "n"(N));
}

// ---------------------------------------------------------------------------
// Prep kernels (one-time conversions; all GEMM fills become raw cp.async)
// ---------------------------------------------------------------------------
__global__ void prep_x(const float* __restrict__ x) {
    int i = blockIdx.x * blockDim.x + threadIdx.x;   // over MM*HH/4
    float4 v = ((const float4*)x)[i];
    ((uint4*)g_xTF)[i] = make_uint4(f2tf32(v.x), f2tf32(v.y), f2tf32(v.z), f2tf32(v.w));
    uint32_t h0, l0, h1, l1;
    bfsplit2(v.x, v.y, h0, l0);
    bfsplit2(v.z, v.w, h1, l1);
    ((uint4*)g_xHL)[i] = make_uint4(h0, l0, h1, l1);
}
__global__ void prep_wd(const float* __restrict__ Wq, const float* __restrict__ Wk,
                        const float* __restrict__ bq, const float* __restrict__ bk) {
    int i = blockIdx.x * blockDim.x + threadIdx.x;   // over 512*1024
    int p = i >> 10, n = i & 1023;
    float a0 = Wq[(size_t)(2*p)   * HH + n] - Wk[(size_t)(2*p)   * HH + n];
    float a1 = Wq[(size_t)(2*p+1) * HH + n] - Wk[(size_t)(2*p+1) * HH + n];
    uint32_t h, l; bfsplit2(a0, a1, h, l);
    *(uint2*)&g_WdHL[(size_t)p * 2048 + 2*n] = make_uint2(h, l);
    if (i < HH) g_bd[i] = bq[i] - bk[i];
}
__global__ void prep_tf(const float* __restrict__ src, uint32_t* __restrict__ dst) {
    int i = blockIdx.x * blockDim.x + threadIdx.x;   // over HH*HH/4
    float4 v = ((const float4*)src)[i];
    ((uint4*)dst)[i] = make_uint4(f2tf32(v.x), f2tf32(v.y), f2tf32(v.z), f2tf32(v.w));
}

// ---------------------------------------------------------------------------
// tf32 GEMM, cp.async double-buffered, zero cvt in kernel.
// A: u32 tf32 [M][1024]; W: u32 tf32 [1024][1024]; block 128x128, 8 warps.
// As [m][20] (stride 4*odd -> conflict-free), Bs [k][136].
// MODE 0: fp32 out (final).  MODE 3: V out -> g_VtP transposed+permuted tf32.
// ---------------------------------------------------------------------------
template<int MODE>
__global__ __launch_bounds__(256) void gemm_tc(const uint32_t* __restrict__ A,
                                               const uint32_t* __restrict__ W,
                                               const float* __restrict__ bias,
                                               void* __restrict__ Cout) {
    const int ASZ = 128 * 20, BSZ = 16 * 136;
    __shared__ uint32_t As[2 * ASZ];
    __shared__ uint32_t Bs[2 * BSZ];
    int tid = threadIdx.x, lane = tid & 31, w = tid >> 5;
    int la3 = lane & 3, l4 = lane >> 2;
    int wm = (w & 1) * 64, wn = (w >> 1) * 32;
    int row0 = blockIdx.y * 128, col0 = blockIdx.x * 128;

    uint32_t asb = smem_u32(As), bsb = smem_u32(Bs);
    float acc[4][4][4] = {};

    #define G_FILL(T) do {                                                       \
        int k0 = (T) * 16, bf = (T) & 1;                                         \
        _Pragma("unroll")                                                        \
        for (int i = 0; i < 2; i++) {                                            \
            int f = tid + i * 256;                                               \
            int r = f >> 2, j = f & 3;                                           \
            cp16(asb + (bf * ASZ + r * 20 + 4 * j) * 4,                          \
                 A + (size_t)(row0 + r) * HH + k0 + 4 * j);                      \
        }                                                                        \
        _Pragma("unroll")                                                        \
        for (int i = 0; i < 2; i++) {                                            \
            int f = tid + i * 256;                                               \
            int r = f >> 5, j = f & 31;                                          \
            cp16(bsb + (bf * BSZ + r * 136 + 4 * j) * 4,                         \
                 W + (size_t)(k0 + r) * HH + col0 + 4 * j);                      \
        }                                                                        \
    } while (0)

    G_FILL(0); cp_commit();

    for (int t = 0; t < HH / 16; t++) {
        if (t + 1 < HH / 16) { G_FILL(t + 1); cp_commit(); cp_wait<1>(); }
        else                 { cp_wait<0>(); }
        __syncthreads();
        const uint32_t* Ab = As + (t & 1) * ASZ;
        const uint32_t* Bb = Bs + (t & 1) * BSZ;

        #pragma unroll
        for (int kk = 0; kk < 16; kk += 8) {
            int rc = (kk + la3) * 136, rd = (kk + 4 + la3) * 136;
            uint32_t bf[4][2];
            #pragma unroll
            for (int nt = 0; nt < 4; nt++) {
                int n = wn + nt * 8 + l4;
                bf[nt][0] = Bb[rc + n];
                bf[nt][1] = Bb[rd + n];
            }
            #pragma unroll
            for (int mt = 0; mt < 4; mt++) {
                int m = wm + mt * 16 + l4;
                uint32_t a0 = Ab[m * 20 + kk + la3];
                uint32_t a1 = Ab[(m + 8) * 20 + kk + la3];
                uint32_t a2 = Ab[m * 20 + kk + 4 + la3];
                uint32_t a3 = Ab[(m + 8) * 20 + kk + 4 + la3];
                #pragma unroll
                for (int nt = 0; nt < 4; nt++)
                    mma8(acc[mt][nt], a0, a1, a2, a3, bf[nt][0], bf[nt][1]);
            }
        }
        __syncthreads();
    }
    #undef G_FILL

    #pragma unroll
    for (int mt = 0; mt < 4; mt++) {
        int r = row0 + wm + mt * 16 + l4;
        #pragma unroll
        for (int nt = 0; nt < 4; nt++) {
            int cb = col0 + wn + nt * 8 + 2 * la3;
            float v0 = acc[mt][nt][0] + bias[cb];
            float v1 = acc[mt][nt][1] + bias[cb + 1];
            float v2 = acc[mt][nt][2] + bias[cb];
            float v3 = acc[mt][nt][3] + bias[cb + 1];
            if (MODE == 0) {
                float* C = (float*)Cout;
                C[(size_t)r       * HH + cb    ] = v0;
                C[(size_t)r       * HH + cb + 1] = v1;
                C[(size_t)(r + 8) * HH + cb    ] = v2;
                C[(size_t)(r + 8) * HH + cb + 1] = v3;
            } else {
                // V: write transposed + key-permuted tf32 into g_VtP
                uint32_t* VtP = (uint32_t*)Cout;
                int bI = r >> 11, s = r & 2047;
                int hI = cb >> 6, d = cb & 63;
                int pos = (s & ~7) + 2 * (s & 3) + ((s >> 2) & 1);
                size_t hb = (size_t)(bI * NH + hI) * HD;
                VtP[(hb + d)     * SS + pos    ] = f2tf32(v0);
                VtP[(hb + d + 1) * SS + pos    ] = f2tf32(v1);
                VtP[(hb + d)     * SS + pos + 8] = f2tf32(v2);
                VtP[(hb + d + 1) * SS + pos + 8] = f2tf32(v3);
            }
        }
    }
}

// ---------------------------------------------------------------------------
// D = x @ Wd + bd in 3xBF16 (m16n8k16), cp.async double-buffered, zero cvt.
// Inputs pre-split pair-interleaved (g_xHL, g_WdHL). BK=32 (16 pairs).
// As [m][40] hi/lo interleaved; Bs [p][264] hi/lo interleaved. LDS.64 frags.
// Output g_DHL (bf16 hi/lo pair-interleaved).
// ---------------------------------------------------------------------------
__global__ __launch_bounds__(256) void gemm_bf3(const uint32_t* __restrict__ AHL,
                                                const uint32_t* __restrict__ WHL,
                                                const float* __restrict__ bias,
                                                uint32_t* __restrict__ Dout) {
    extern __shared__ uint32_t sm[];
    const int ASZ = 128 * 40, BSZ = 16 * 264;
    uint32_t* Asm = sm;                 // 2 x ASZ
    uint32_t* Bsm = sm + 2 * ASZ;       // 2 x BSZ
    int tid = threadIdx.x, lane = tid & 31, w = tid >> 5;
    int la3 = lane & 3, l4 = lane >> 2;
    int wm = (w & 1) * 64, wn = (w >> 1) * 32;
    int row0 = blockIdx.y * 128, col0 = blockIdx.x * 128;

    uint32_t asb = smem_u32(Asm), bsb = smem_u32(Bsm);
    float acc[4][4][4] = {};

    #define B_FILL(T) do {                                                       \
        int u0 = (T) * 32, p0 = (T) * 16, bf = (T) & 1;                          \
        _Pragma("unroll")                                                        \
        for (int i = 0; i < 4; i++) {                                            \
            int f = tid + i * 256;                                               \
            int r = f >> 3, j = f & 7;                                           \
            cp16(asb + (bf * ASZ + r * 40 + 4 * j) * 4,                          \
                 AHL + (size_t)(row0 + r) * HH + u0 + 4 * j);                    \
        }                                                                        \
        _Pragma("unroll")                                                        \
        for (int i = 0; i < 4; i++) {                                            \
            int f = tid + i * 256;                                               \
            int p = f >> 6, j = f & 63;                                          \
            cp16(bsb + (bf * BSZ + p * 264 + 4 * j) * 4,                         \
                 WHL + (size_t)(p0 + p) * 2048 + 2 * col0 + 4 * j);              \
        }                                                                        \
    } while (0)

    B_FILL(0); cp_commit();

    for (int t = 0; t < HH / 32; t++) {
        if (t + 1 < HH / 32) { B_FILL(t + 1); cp_commit(); cp_wait<1>(); }
        else                 { cp_wait<0>(); }
        __syncthreads();
        const uint32_t* Ab = Asm + (t & 1) * ASZ;
        const uint32_t* Bb = Bsm + (t & 1) * BSZ;

        #pragma unroll
        for (int K = 0; K < 2; K++) {
            int pb = K * 8;
            uint2 Bf0[4], Bf1[4];
            #pragma unroll
            for (int nt = 0; nt < 4; nt++) {
                int n = wn + nt * 8 + l4;
                Bf0[nt] = *(const uint2*)&Bb[(pb + la3)     * 264 + 2 * n];
                Bf1[nt] = *(const uint2*)&Bb[(pb + 4 + la3) * 264 + 2 * n];
            }
            #pragma unroll
            for (int mt = 0; mt < 4; mt++) {
                int m = wm + mt * 16 + l4;
                uint2 A0 = *(const uint2*)&Ab[m       * 40 + 2 * (pb + la3)];
                uint2 A1 = *(const uint2*)&Ab[(m + 8) * 40 + 2 * (pb + la3)];
                uint2 A2 = *(const uint2*)&Ab[m       * 40 + 2 * (pb + 4 + la3)];
                uint2 A3 = *(const uint2*)&Ab[(m + 8) * 40 + 2 * (pb + 4 + la3)];
                #pragma unroll
                for (int nt = 0; nt < 4; nt++) {
                    mma16(acc[mt][nt], A0.x, A1.x, A2.x, A3.x, Bf0[nt].x, Bf1[nt].x);
                    mma16(acc[mt][nt], A0.x, A1.x, A2.x, A3.x, Bf0[nt].y, Bf1[nt].y);
                    mma16(acc[mt][nt], A0.y, A1.y, A2.y, A3.y, Bf0[nt].x, Bf1[nt].x);
                }
            }
        }
        __syncthreads();
    }
    #undef B_FILL

    #pragma unroll
    for (int mt = 0; mt < 4; mt++) {
        int r = row0 + wm + mt * 16 + l4;
        #pragma unroll
        for (int nt = 0; nt < 4; nt++) {
            int cb = col0 + wn + nt * 8 + 2 * la3;
            float v0 = acc[mt][nt][0] + bias[cb];
            float v1 = acc[mt][nt][1] + bias[cb + 1];
            float v2 = acc[mt][nt][2] + bias[cb];
            float v3 = acc[mt][nt][3] + bias[cb + 1];
            uint32_t h, l;
            bfsplit2(v0, v1, h, l);
            *(uint2*)&Dout[(size_t)r * HH + cb] = make_uint2(h, l);
            bfsplit2(v2, v3, h, l);
            *(uint2*)&Dout[(size_t)(r + 8) * HH + cb] = make_uint2(h, l);
        }
    }
}

// ---------------------------------------------------------------------------
// Fused anti-causal gaussian attention. QK 3xBF16 (m16n8k16), PV tf32.
// K-tile 64, software-pipelined single-buffer fills (R7, proven).
// Epilogue writes ctx as tf32 u32 (feeds cp.async O-GEMM).
// ---------------------------------------------------------------------------
__global__ __launch_bounds__(128, 4) void attn_tc(const uint32_t* __restrict__ DH,
                                                  const uint32_t* __restrict__ VtP,
                                                  uint32_t* __restrict__ C) {
    extern __shared__ uint32_t sm[];
    const int DK0 = 0;                 // [64][72] bf16 hi/lo pair-interleaved
    const int VT0 = 64 * 72;           // [64][72] tf32, permuted keys
    const int PS0 = VT0 + 64 * 72;     // [64][72] tf32, permuted keys

    int tid = threadIdx.x, lane = tid & 31, w = tid >> 5;
    int la3 = lane & 3, l4 = lane >> 2;
    int q0 = blockIdx.x * 64, h = blockIdx.y, b = blockIdx.z;
    const uint32_t* DHb = DH + (size_t)b * SS * HH + h * 64;
    const uint32_t* Vb  = VtP + (size_t)(b * NH + h) * HD * SS;
    int qrow = w * 16 + l4;

    uint32_t smb = smem_u32(sm);
    uint32_t dkb = smb + DK0 * 4;
    uint32_t vtb = smb + VT0 * 4;

    // Q-side fragments: packed bf16 hi/lo, loaded once (loop-invariant)
    uint32_t aH[4][4], aL[4][4];
    {
        const uint32_t* r0 = DHb + (size_t)(q0 + qrow) * HH;
        const uint32_t* r8 = r0 + (size_t)8 * HH;
        #pragma unroll
        for (int K = 0; K < 4; K++) {
            uint2 A0 = *(const uint2*)&r0[2 * (K * 8 + la3)];
            uint2 A1 = *(const uint2*)&r8[2 * (K * 8 + la3)];
            uint2 A2 = *(const uint2*)&r0[2 * (K * 8 + 4 + la3)];
            uint2 A3 = *(const uint2*)&r8[2 * (K * 8 + 4 + la3)];
            aH[K][0] = A0.x; aL[K][0] = A0.y;
            aH[K][1] = A1.x; aL[K][1] = A1.y;
            aH[K][2] = A2.x; aL[K][2] = A2.y;
            aH[K][3] = A3.x; aL[K][3] = A3.y;
        }
    }

    int r8a = 2 * la3, r8b = 2 * la3 + 1;
    int pA = 2 * (r8a & 3) + ((r8a >> 2) & 1);
    int pB = 2 * (r8b & 3) + ((r8b >> 2) & 1);

    float ctx[8][4] = {};
    int nT = (SS - q0) / 64;

    #define FILL_DK(T) do {                                                      \
        int k0t = q0 + (T) * 64;                                                 \
        _Pragma("unroll")                                                        \
        for (int i = 0; i < 8; i++) {                                            \
            int idx = tid + i * 128;                                             \
            int r = idx >> 4, j = idx & 15;                                      \
            cp16(dkb + (r * 72 + 4 * j) * 4,                                     \
                 DHb + (size_t)(k0t + r) * HH + 4 * j);                          \
        }                                                                        \
    } while (0)
    #define FILL_V(T) do {                                                       \
        int k0t = q0 + (T) * 64;                                                 \
        _Pragma("unroll")                                                        \
        for (int i = 0; i < 8; i++) {                                            \
            int idx = tid + i * 128;                                             \
            int d = idx >> 4, j = idx & 15;                                      \
            cp16(vtb + (d * 72 + 4 * j) * 4,                                     \
                 Vb + (size_t)d * SS + k0t + 4 * j);                             \
        }                                                                        \
    } while (0)

    FILL_DK(0); cp_commit();
    FILL_V(0);  cp_commit();

    for (int t = 0; t < nT; t++) {
        int k0 = q0 + t * 64;
        cp_wait<1>();          // Dk(t) resident
        __syncthreads();

        const uint32_t* Dk = sm + DK0;
        const uint32_t* Vp = sm + VT0;
        uint32_t* Pw = sm + PS0;

        // ---- QK: S[16q x 64k] per warp, 3xBF16 over d=64 ----
        float s4[8][4] = {};
        #pragma unroll
        for (int K = 0; K < 4; K++) {
            #pragma unroll
            for (int nt = 0; nt < 8; nt++) {
                const uint32_t* br = Dk + (nt * 8 + l4) * 72;
                uint2 P0 = *(const uint2*)&br[2 * (K * 8 + la3)];
                uint2 P1 = *(const uint2*)&br[2 * (K * 8 + 4 + la3)];
                mma16(s4[nt], aH[K][0], aH[K][1], aH[K][2], aH[K][3], P0.x, P1.x);
                mma16(s4[nt], aH[K][0], aH[K][1], aH[K][2], aH[K][3], P0.y, P1.y);
                mma16(s4[nt], aL[K][0], aL[K][1], aL[K][2], aL[K][3], P0.x, P1.x);
            }
        }

        __syncthreads();                       // all warps done reading Dk
        if (t + 1 < nT) FILL_DK(t + 1);        // overlaps mask + PV
        cp_commit();

        // ---- mask (k > q strictly) + exp -> Ps (permuted cols, tf32) ----
        #pragma unroll
        for (int nt = 0; nt < 8; nt++) {
            int kgA = k0 + nt * 8 + r8a;
            float p0 = (kgA     > q0 + qrow)     ? __expf(-0.5f * s4[nt][0]) : 0.0f;
            float p1 = (kgA + 1 > q0 + qrow)     ? __expf(-0.5f * s4[nt][1]) : 0.0f;
            float p2 = (kgA     > q0 + qrow + 8) ? __expf(-0.5f * s4[nt][2]) : 0.0f;
            float p3 = (kgA + 1 > q0 + qrow + 8) ? __expf(-0.5f * s4[nt][3]) : 0.0f;
            Pw[qrow * 72 + nt * 8 + pA]       = f2tf32(p0);
            Pw[qrow * 72 + nt * 8 + pB]       = f2tf32(p1);
            Pw[(qrow + 8) * 72 + nt * 8 + pA] = f2tf32(p2);
            Pw[(qrow + 8) * 72 + nt * 8 + pB] = f2tf32(p3);
        }
        __syncwarp();   // Pw rows are warp-private

        cp_wait<1>();          // V(t) resident
        __syncthreads();

        // ---- PV: ctx[16q x 64d] += P @ V over 64 keys (all LDS.64, tf32) ----
        #pragma unroll
        for (int kt = 0; kt < 8; kt++) {
            int kk = kt * 8;
            uint2 ua = *(const uint2*)&Pw[qrow * 72 + kk + 2 * la3];
            uint2 ub = *(const uint2*)&Pw[(qrow + 8) * 72 + kk + 2 * la3];
            #pragma unroll
            for (int nt = 0; nt < 8; nt++) {
                uint2 vb2 = *(const uint2*)&Vp[(nt * 8 + l4) * 72 + kk + 2 * la3];
                mma8(ctx[nt], ua.x, ub.x, ua.y, ub.y, vb2.x, vb2.y);
            }
        }

        __syncthreads();                       // all warps done reading Vp/Ps
        if (t + 1 < nT) FILL_V(t + 1);         // overlaps next QK
        cp_commit();
    }

    // Store ctx as tf32 in merged [B,S,H] layout
    uint32_t* Cb = C + (size_t)b * SS * HH + h * HD;
    #pragma unroll
    for (int nt = 0; nt < 8; nt++) {
        int r = q0 + qrow;
        int c = nt * 8 + 2 * la3;
        *(uint2*)&Cb[(size_t)r       * HH + c] = make_uint2(f2tf32(ctx[nt][0]), f2tf32(ctx[nt][1]));
        *(uint2*)&Cb[(size_t)(r + 8) * HH + c] = make_uint2(f2tf32(ctx[nt][2]), f2tf32(ctx[nt][3]));
    }
    #undef FILL_DK
    #undef FILL_V
}

static const int ATTN_SMEM = (3 * 64 * 72) * 4;                  // 55296 B
static const int BF3_SMEM  = (2 * 128 * 40 + 2 * 16 * 264) * 4;  // 74752 B

extern "C" void kernel_launch(void* const* d_in, const int* in_sizes, int n_in,
                              void* d_out, int out_size) {
    const float* x  = (const float*)d_in[0];
    const float* Wq = (const float*)d_in[1];
    const float* bq = (const float*)d_in[2];
    const float* Wk = (const float*)d_in[3];
    const float* bk = (const float*)d_in[4];
    const float* Wv = (const float*)d_in[5];
    const float* bv = (const float*)d_in[6];
    const float* Wo = (const float*)d_in[7];
    const float* bo = (const float*)d_in[8];
    float* out = (float*)d_out;

    uint32_t *pxTF, *pxHL, *pWdHL, *pWvTF, *pWoTF, *pDHL, *pVtP, *pC;
    float *pbd;
    cudaGetSymbolAddress((void**)&pxTF,  g_xTF);
    cudaGetSymbolAddress((void**)&pxHL,  g_xHL);
    cudaGetSymbolAddress((void**)&pWdHL, g_WdHL);
    cudaGetSymbolAddress((void**)&pWvTF, g_WvTF);
    cudaGetSymbolAddress((void**)&pWoTF, g_WoTF);
    cudaGetSymbolAddress((void**)&pbd,   g_bd);
    cudaGetSymbolAddress((void**)&pDHL,  g_DHL);
    cudaGetSymbolAddress((void**)&pVtP,  g_VtP);
    cudaGetSymbolAddress((void**)&pC,    g_C);

    static bool attr_set = false;
    if (!attr_set) {
        cudaFuncSetAttribute(attn_tc, cudaFuncAttributeMaxDynamicSharedMemorySize, ATTN_SMEM);
        cudaFuncSetAttribute(gemm_bf3, cudaFuncAttributeMaxDynamicSharedMemorySize, BF3_SMEM);
        attr_set = true;
    }

    // 1. prep: x -> tf32 + bf16 hi/lo; Wd -> bf16 hi/lo; Wv/Wo -> tf32; bd
    prep_x <<<(MM * HH / 4) / 256, 256>>>(x);
    prep_wd<<<(512 * 1024) / 256, 256>>>(Wq, Wk, bq, bk);
    prep_tf<<<(HH * HH / 4) / 256, 256>>>(Wv, pWvTF);
    prep_tf<<<(HH * HH / 4) / 256, 256>>>(Wo, pWoTF);

    // 2. D = x @ Wd + bd (3xBF16) ; V = x @ Wv + bv (tf32, direct VtP out)
    dim3 ggrid(HH / 128, MM / 128);
    gemm_bf3<<<ggrid, 256, BF3_SMEM>>>(pxHL, pWdHL, pbd, pDHL);
    gemm_tc<3><<<ggrid, 256>>>(pxTF, pWvTF, bv, pVtP);

    // 3. fused attention -> ctx (tf32) in [B,S,H] layout
    dim3 agrid(SS / 64, NH, BB);
    attn_tc<<<agrid, 128, ATTN_SMEM>>>(pDHL, pVtP, pC);

    // 4. out = ctx @ Wo + bo (tf32)
    gemm_tc<0><<<ggrid, 256>>>(pC, pWoTF, bo, out);
}

// round 9
// speedup vs baseline: 1.7884x; 1.1119x over previous
#include <cuda_runtime.h>
#include <cuda_bf16.h>
#include <cstdint>

#define BB 2
#define SS 2048
#define HH 1024
#define NH 16
#define HD 64
#define MM (BB*SS)   // 4096 rows

// Scratch (allocation is forbidden; use __device__ globals)
__device__ uint32_t g_xTF[(size_t)MM*HH];         // x as tf32
__device__ uint32_t g_xHL[(size_t)MM*HH];         // x as bf16 hi/lo pair-interleaved
__device__ uint32_t g_WdHL[(size_t)(HH/2)*2*HH];  // Wq-Wk, bf16 hi/lo: [512 k-pairs][2048]
__device__ uint32_t g_WvTF[(size_t)HH*HH];        // Wv as tf32
__device__ uint32_t g_WoTF[(size_t)HH*HH];        // Wo as tf32
__device__ float    g_bd[HH];
__device__ uint32_t g_DHL[(size_t)MM*HH];         // D, bf16 hi/lo, quad-permuted per head
__device__ uint32_t g_VtP[(size_t)BB*NH*HD*SS];   // V^T tf32, keys in PHI order, per (b,h)
__device__ uint32_t g_C[(size_t)MM*HH];           // ctx as tf32

__device__ __forceinline__ uint32_t f2tf32(float x) {
    uint32_t r;
    asm("cvt.rna.tf32.f32 %0, %1;" : "=r"(r) : "f"(x));
    return r;
}
__device__ __forceinline__ uint32_t bfpack(float x0, float x1) {
    __nv_bfloat162 t;
    t.x = __float2bfloat16_rn(x0);
    t.y = __float2bfloat16_rn(x1);
    return *(uint32_t*)&t;
}
__device__ __forceinline__ void bfsplit2(float x0, float x1, uint32_t& hi, uint32_t& lo) {
    __nv_bfloat16 h0 = __float2bfloat16_rn(x0), h1 = __float2bfloat16_rn(x1);
    float r0 = x0 - __bfloat162float(h0), r1 = x1 - __bfloat162float(h1);
    __nv_bfloat162 th; th.x = h0; th.y = h1;
    hi = *(uint32_t*)&th;
    lo = bfpack(r0, r1);
}
__device__ __forceinline__ void mma8(float* c,
                                     uint32_t a0, uint32_t a1, uint32_t a2, uint32_t a3,
                                     uint32_t b0, uint32_t b1) {
    asm volatile(
        "mma.sync.aligned.m16n8k8.row.col.f32.tf32.tf32.f32 "
        "{%0,%1,%2,%3}, {%4,%5,%6,%7}, {%8,%9}, {%0,%1,%2,%3};"
        : "+f"(c[0]), "+f"(c[1]), "+f"(c[2]), "+f"(c[3])
        : "r"(a0), "r"(a1), "r"(a2), "r"(a3), "r"(b0), "r"(b1));
}
__device__ __forceinline__ void mma16(float* c,
                                      uint32_t a0, uint32_t a1, uint32_t a2, uint32_t a3,
                                      uint32_t b0, uint32_t b1) {
    asm volatile(
        "mma.sync.aligned.m16n8k16.row.col.f32.bf16.bf16.f32 "
        "{%0,%1,%2,%3}, {%4,%5,%6,%7}, {%8,%9}, {%0,%1,%2,%3};"
        : "+f"(c[0]), "+f"(c[1]), "+f"(c[2]), "+f"(c[3])
        : "r"(a0), "r"(a1), "r"(a2), "r"(a3), "r"(b0), "r"(b1));
}
__device__ __forceinline__ uint32_t smem_u32(const void* p) {
    uint32_t a;
    asm("{ .reg .u64 t; cvta.to.shared.u64 t, %1; cvt.u32.u64 %0, t; }" : "=r"(a) : "l"(p));
    return a;
}
__device__ __forceinline__ void cp16(uint32_t dst, const void* src) {
    asm volatile("cp.async.ca.shared.global [%0], [%1], 16;" :: "r"(dst), "l"(src));
}
__device__ __forceinline__ void cp_commit() { asm volatile("cp.async.commit_group;"); }
template<int N> __device__ __forceinline__ void cp_wait() {
    asm volatile("cp.async.wait_group %0;" :: "n"(N));
}

// ---------------------------------------------------------------------------
// Prep kernels
// ---------------------------------------------------------------------------
__global__ void prep_x(const float* __restrict__ x) {
    int i = blockIdx.x * blockDim.x + threadIdx.x;   // over MM*HH/4
    float4 v = ((const float4*)x)[i];
    ((uint4*)g_xTF)[i] = make_uint4(f2tf32(v.x), f2tf32(v.y), f2tf32(v.z), f2tf32(v.w));
    uint32_t h0, l0, h1, l1;
    bfsplit2(v.x, v.y, h0, l0);
    bfsplit2(v.z, v.w, h1, l1);
    ((uint4*)g_xHL)[i] = make_uint4(h0, l0, h1, l1);
}
__global__ void prep_wd(const float* __restrict__ Wq, const float* __restrict__ Wk,
                        const float* __restrict__ bq, const float* __restrict__ bk) {
    int i = blockIdx.x * blockDim.x + threadIdx.x;   // over 512*1024
    int p = i >> 10, n = i & 1023;
    float a0 = Wq[(size_t)(2*p)   * HH + n] - Wk[(size_t)(2*p)   * HH + n];
    float a1 = Wq[(size_t)(2*p+1) * HH + n] - Wk[(size_t)(2*p+1) * HH + n];
    uint32_t h, l; bfsplit2(a0, a1, h, l);
    *(uint2*)&g_WdHL[(size_t)p * 2048 + 2*n] = make_uint2(h, l);
    if (i < HH) g_bd[i] = bq[i] - bk[i];
}
__global__ void prep_tf2(const float* __restrict__ s0, uint32_t* __restrict__ d0,
                         const float* __restrict__ s1, uint32_t* __restrict__ d1) {
    int i = blockIdx.x * blockDim.x + threadIdx.x;   // over HH*HH/4
    const float* src = blockIdx.y ? s1 : s0;
    uint32_t* dst = blockIdx.y ? d1 : d0;
    float4 v = ((const float4*)src)[i];
    ((uint4*)dst)[i] = make_uint4(f2tf32(v.x), f2tf32(v.y), f2tf32(v.z), f2tf32(v.w));
}

// ---------------------------------------------------------------------------
// tf32 GEMM, cp.async double-buffered, zero cvt in kernel.
// MODE 0: fp32 out (final). MODE 3: V out -> g_VtP transposed, keys PHI-permuted.
// PHI(t) = 16*(t>>4) + 4*((t>>1)&3) + 2*((t>>3)&1) + (t&1)
// ---------------------------------------------------------------------------
template<int MODE>
__global__ __launch_bounds__(256) void gemm_tc(const uint32_t* __restrict__ A,
                                               const uint32_t* __restrict__ W,
                                               const float* __restrict__ bias,
                                               void* __restrict__ Cout) {
    const int ASZ = 128 * 20, BSZ = 16 * 136;
    __shared__ uint32_t As[2 * ASZ];
    __shared__ uint32_t Bs[2 * BSZ];
    int tid = threadIdx.x, lane = tid & 31, w = tid >> 5;
    int la3 = lane & 3, l4 = lane >> 2;
    int wm = (w & 1) * 64, wn = (w >> 1) * 32;
    int row0 = blockIdx.y * 128, col0 = blockIdx.x * 128;

    uint32_t asb = smem_u32(As), bsb = smem_u32(Bs);
    float acc[4][4][4] = {};

    #define G_FILL(T) do {                                                       \
        int k0 = (T) * 16, bf = (T) & 1;                                         \
        _Pragma("unroll")                                                        \
        for (int i = 0; i < 2; i++) {                                            \
            int f = tid + i * 256;                                               \
            int r = f >> 2, j = f & 3;                                           \
            cp16(asb + (bf * ASZ + r * 20 + 4 * j) * 4,                          \
                 A + (size_t)(row0 + r) * HH + k0 + 4 * j);                      \
        }                                                                        \
        _Pragma("unroll")                                                        \
        for (int i = 0; i < 2; i++) {                                            \
            int f = tid + i * 256;                                               \
            int r = f >> 5, j = f & 31;                                          \
            cp16(bsb + (bf * BSZ + r * 136 + 4 * j) * 4,                         \
                 W + (size_t)(k0 + r) * HH + col0 + 4 * j);                      \
        }                                                                        \
    } while (0)

    G_FILL(0); cp_commit();

    for (int t = 0; t < HH / 16; t++) {
        if (t + 1 < HH / 16) { G_FILL(t + 1); cp_commit(); cp_wait<1>(); }
        else                 { cp_wait<0>(); }
        __syncthreads();
        const uint32_t* Ab = As + (t & 1) * ASZ;
        const uint32_t* Bb = Bs + (t & 1) * BSZ;

        #pragma unroll
        for (int kk = 0; kk < 16; kk += 8) {
            int rc = (kk + la3) * 136, rd = (kk + 4 + la3) * 136;
            uint32_t bf[4][2];
            #pragma unroll
            for (int nt = 0; nt < 4; nt++) {
                int n = wn + nt * 8 + l4;
                bf[nt][0] = Bb[rc + n];
                bf[nt][1] = Bb[rd + n];
            }
            #pragma unroll
            for (int mt = 0; mt < 4; mt++) {
                int m = wm + mt * 16 + l4;
                uint32_t a0 = Ab[m * 20 + kk + la3];
                uint32_t a1 = Ab[(m + 8) * 20 + kk + la3];
                uint32_t a2 = Ab[m * 20 + kk + 4 + la3];
                uint32_t a3 = Ab[(m + 8) * 20 + kk + 4 + la3];
                #pragma unroll
                for (int nt = 0; nt < 4; nt++)
                    mma8(acc[mt][nt], a0, a1, a2, a3, bf[nt][0], bf[nt][1]);
            }
        }
        __syncthreads();
    }
    #undef G_FILL

    #pragma unroll
    for (int mt = 0; mt < 4; mt++) {
        int r = row0 + wm + mt * 16 + l4;
        #pragma unroll
        for (int nt = 0; nt < 4; nt++) {
            int cb = col0 + wn + nt * 8 + 2 * la3;
            float v0 = acc[mt][nt][0] + bias[cb];
            float v1 = acc[mt][nt][1] + bias[cb + 1];
            float v2 = acc[mt][nt][2] + bias[cb];
            float v3 = acc[mt][nt][3] + bias[cb + 1];
            if (MODE == 0) {
                float* C = (float*)Cout;
                C[(size_t)r       * HH + cb    ] = v0;
                C[(size_t)r       * HH + cb + 1] = v1;
                C[(size_t)(r + 8) * HH + cb    ] = v2;
                C[(size_t)(r + 8) * HH + cb + 1] = v3;
            } else {
                // V: transposed, keys PHI-permuted (r&15 = l4 < 8, so PHI(r+8)=PHI(r)+2)
                uint32_t* VtP = (uint32_t*)Cout;
                int bI = r >> 11, s = r & 2047;
                int hI = cb >> 6, d = cb & 63;
                int pos = 16 * (s >> 4) + 4 * ((s >> 1) & 3) + 2 * ((s >> 3) & 1) + (s & 1);
                size_t hb = (size_t)(bI * NH + hI) * HD;
                VtP[(hb + d)     * SS + pos    ] = f2tf32(v0);
                VtP[(hb + d + 1) * SS + pos    ] = f2tf32(v1);
                VtP[(hb + d)     * SS + pos + 2] = f2tf32(v2);
                VtP[(hb + d + 1) * SS + pos + 2] = f2tf32(v3);
            }
        }
    }
}

// ---------------------------------------------------------------------------
// D = x @ Wd + bd in 3xBF16 (m16n8k16), cp.async double-buffered.
// Output: per head 64 u32, quad-permuted: pair q (=8o+j) of head -> u32
// offset head*64 + 16*o + 4*(j&3) + 2*((j>>2)&1), {hi,lo} adjacent.
// ---------------------------------------------------------------------------
__global__ __launch_bounds__(256) void gemm_bf3(const uint32_t* __restrict__ AHL,
                                                const uint32_t* __restrict__ WHL,
                                                const float* __restrict__ bias,
                                                uint32_t* __restrict__ Dout) {
    extern __shared__ uint32_t sm[];
    const int ASZ = 128 * 40, BSZ = 16 * 264;
    uint32_t* Asm = sm;
    uint32_t* Bsm = sm + 2 * ASZ;
    int tid = threadIdx.x, lane = tid & 31, w = tid >> 5;
    int la3 = lane & 3, l4 = lane >> 2;
    int wm = (w & 1) * 64, wn = (w >> 1) * 32;
    int row0 = blockIdx.y * 128, col0 = blockIdx.x * 128;

    uint32_t asb = smem_u32(Asm), bsb = smem_u32(Bsm);
    float acc[4][4][4] = {};

    #define B_FILL(T) do {                                                       \
        int u0 = (T) * 32, p0 = (T) * 16, bf = (T) & 1;                          \
        _Pragma("unroll")                                                        \
        for (int i = 0; i < 4; i++) {                                            \
            int f = tid + i * 256;                                               \
            int r = f >> 3, j = f & 7;                                           \
            cp16(asb + (bf * ASZ + r * 40 + 4 * j) * 4,                          \
                 AHL + (size_t)(row0 + r) * HH + u0 + 4 * j);                    \
        }                                                                        \
        _Pragma("unroll")                                                        \
        for (int i = 0; i < 4; i++) {                                            \
            int f = tid + i * 256;                                               \
            int p = f >> 6, j = f & 63;                                          \
            cp16(bsb + (bf * BSZ + p * 264 + 4 * j) * 4,                         \
                 WHL + (size_t)(p0 + p) * 2048 + 2 * col0 + 4 * j);              \
        }                                                                        \
    } while (0)

    B_FILL(0); cp_commit();

    for (int t = 0; t < HH / 32; t++) {
        if (t + 1 < HH / 32) { B_FILL(t + 1); cp_commit(); cp_wait<1>(); }
        else                 { cp_wait<0>(); }
        __syncthreads();
        const uint32_t* Ab = Asm + (t & 1) * ASZ;
        const uint32_t* Bb = Bsm + (t & 1) * BSZ;

        #pragma unroll
        for (int K = 0; K < 2; K++) {
            int pb = K * 8;
            uint2 Bf0[4], Bf1[4];
            #pragma unroll
            for (int nt = 0; nt < 4; nt++) {
                int n = wn + nt * 8 + l4;
                Bf0[nt] = *(const uint2*)&Bb[(pb + la3)     * 264 + 2 * n];
                Bf1[nt] = *(const uint2*)&Bb[(pb + 4 + la3) * 264 + 2 * n];
            }
            #pragma unroll
            for (int mt = 0; mt < 4; mt++) {
                int m = wm + mt * 16 + l4;
                uint2 A0 = *(const uint2*)&Ab[m       * 40 + 2 * (pb + la3)];
                uint2 A1 = *(const uint2*)&Ab[(m + 8) * 40 + 2 * (pb + la3)];
                uint2 A2 = *(const uint2*)&Ab[m       * 40 + 2 * (pb + 4 + la3)];
                uint2 A3 = *(const uint2*)&Ab[(m + 8) * 40 + 2 * (pb + 4 + la3)];
                #pragma unroll
                for (int nt = 0; nt < 4; nt++) {
                    mma16(acc[mt][nt], A0.x, A1.x, A2.x, A3.x, Bf0[nt].x, Bf1[nt].x);
                    mma16(acc[mt][nt], A0.x, A1.x, A2.x, A3.x, Bf0[nt].y, Bf1[nt].y);
                    mma16(acc[mt][nt], A0.y, A1.y, A2.y, A3.y, Bf0[nt].x, Bf1[nt].x);
                }
            }
        }
        __syncthreads();
    }
    #undef B_FILL

    #pragma unroll
    for (int mt = 0; mt < 4; mt++) {
        int r = row0 + wm + mt * 16 + l4;
        #pragma unroll
        for (int nt = 0; nt < 4; nt++) {
            int cb = col0 + wn + nt * 8 + 2 * la3;
            int p = cb >> 1;                 // global dim-pair index
            int head = p >> 5, q = p & 31;
            int off = head * 64 + 16 * (q >> 3) + 4 * (q & 3) + 2 * ((q >> 2) & 1);
            float v0 = acc[mt][nt][0] + bias[cb];
            float v1 = acc[mt][nt][1] + bias[cb + 1];
            float v2 = acc[mt][nt][2] + bias[cb];
            float v3 = acc[mt][nt][3] + bias[cb + 1];
            uint32_t h, l;
            bfsplit2(v0, v1, h, l);
            *(uint2*)&Dout[(size_t)r * HH + off] = make_uint2(h, l);
            bfsplit2(v2, v3, h, l);
            *(uint2*)&Dout[(size_t)(r + 8) * HH + off] = make_uint2(h, l);
        }
    }
}

// ---------------------------------------------------------------------------
// Fused anti-causal gaussian attention. QK 3xBF16, PV tf32.
// All fragment traffic 128-bit; rows width 64 with ^((row&1)<<4) swizzle.
// Grid: (h, b, qb) with qb SLOWEST -> longest CTAs launch first (LPT).
// Smem: Dk[64][64] + Vp[64][64] + Ps[64][64] = 48KB -> 4 CTAs/SM.
// ---------------------------------------------------------------------------
__global__ __launch_bounds__(128, 4) void attn_tc(const uint32_t* __restrict__ DH,
                                                  const uint32_t* __restrict__ VtP,
                                                  uint32_t* __restrict__ C) {
    extern __shared__ uint32_t sm[];
    const int DK0 = 0;                 // [64][64] bf16 pairs, quad-permuted
    const int VT0 = 64 * 64;           // [64][64] tf32, PHI keys
    const int PS0 = VT0 + 64 * 64;     // [64][64] tf32, PHI keys

    int tid = threadIdx.x, lane = tid & 31, w = tid >> 5;
    int la3 = lane & 3, l4 = lane >> 2;
    int h = blockIdx.x, b = blockIdx.y, q0 = blockIdx.z * 64;
    const uint32_t* DHb = DH + (size_t)b * SS * HH + h * 64;
    const uint32_t* Vb  = VtP + (size_t)(b * NH + h) * HD * SS;
    int qrow = w * 16 + l4;
    int sw = (l4 & 1) << 4;            // row-parity swizzle (qrow, qrow+8 same parity)

    uint32_t smb = smem_u32(sm);
    uint32_t dkb = smb + DK0 * 4;
    uint32_t vtb = smb + VT0 * 4;

    // Q-side fragments: one uint4 per (K, rowhalf) — quad-permuted gmem layout
    uint32_t aH[4][4], aL[4][4];
    {
        const uint32_t* r0 = DHb + (size_t)(q0 + qrow) * HH;
        const uint32_t* r8 = r0 + (size_t)8 * HH;
        #pragma unroll
        for (int K = 0; K < 4; K++) {
            uint4 Q0 = *(const uint4*)&r0[16 * K + 4 * la3];
            uint4 Q8 = *(const uint4*)&r8[16 * K + 4 * la3];
            aH[K][0] = Q0.x; aL[K][0] = Q0.y; aH[K][2] = Q0.z; aL[K][2] = Q0.w;
            aH[K][1] = Q8.x; aL[K][1] = Q8.y; aH[K][3] = Q8.z; aL[K][3] = Q8.w;
        }
    }

    float ctx[8][4] = {};
    int nT = (SS - q0) / 64;

    #define FILL_DK(T) do {                                                      \
        int k0t = q0 + (T) * 64;                                                 \
        _Pragma("unroll")                                                        \
        for (int i = 0; i < 8; i++) {                                            \
            int idx = tid + i * 128;                                             \
            int r = idx >> 4, j = idx & 15;                                      \
            cp16(dkb + (r * 64 + ((4 * j) ^ ((r & 1) << 4))) * 4,                \
                 DHb + (size_t)(k0t + r) * HH + 4 * j);                          \
        }                                                                        \
    } while (0)
    #define FILL_V(T) do {                                                       \
        int k0t = q0 + (T) * 64;                                                 \
        _Pragma("unroll")                                                        \
        for (int i = 0; i < 8; i++) {                                            \
            int idx = tid + i * 128;                                             \
            int d = idx >> 4, j = idx & 15;                                      \
            cp16(vtb + (d * 64 + ((4 * j) ^ ((d & 1) << 4))) * 4,                \
                 Vb + (size_t)d * SS + k0t + 4 * j);                             \
        }                                                                        \
    } while (0)

    FILL_DK(0); cp_commit();
    FILL_V(0);  cp_commit();

    for (int t = 0; t < nT; t++) {
        int k0 = q0 + t * 64;
        cp_wait<1>();          // Dk(t) resident
        __syncthreads();

        const uint32_t* Dk = sm + DK0;
        const uint32_t* Vp = sm + VT0;
        uint32_t* Pw = sm + PS0;

        // ---- QK: S[16q x 64k] per warp, 3xBF16 over d=64 (all LDS.128) ----
        float s4[8][4] = {};
        #pragma unroll
        for (int K = 0; K < 4; K++) {
            #pragma unroll
            for (int nt = 0; nt < 8; nt++) {
                const uint32_t* br = Dk + (nt * 8 + l4) * 64;
                uint4 Dq = *(const uint4*)&br[(16 * K + 4 * la3) ^ sw];
                mma16(s4[nt], aH[K][0], aH[K][1], aH[K][2], aH[K][3], Dq.x, Dq.z);
                mma16(s4[nt], aH[K][0], aH[K][1], aH[K][2], aH[K][3], Dq.y, Dq.w);
                mma16(s4[nt], aL[K][0], aL[K][1], aL[K][2], aL[K][3], Dq.x, Dq.z);
            }
        }

        __syncthreads();                       // all warps done reading Dk
        if (t + 1 < nT) FILL_DK(t + 1);        // overlaps mask + PV
        cp_commit();

        // ---- mask (k > q strictly) + exp -> Ps (PHI layout, STS.128) ----
        #pragma unroll
        for (int kt2 = 0; kt2 < 4; kt2++) {
            int nt0 = 2 * kt2, nt1 = nt0 + 1;
            int kg0 = k0 + nt0 * 8 + 2 * la3;
            int kg1 = k0 + nt1 * 8 + 2 * la3;
            int qa = q0 + qrow, qb8 = qa + 8;
            float e0 = (kg0     > qa) ? __expf(-0.5f * s4[nt0][0]) : 0.0f;
            float e1 = (kg0 + 1 > qa) ? __expf(-0.5f * s4[nt0][1]) : 0.0f;
            float e2 = (kg1     > qa) ? __expf(-0.5f * s4[nt1][0]) : 0.0f;
            float e3 = (kg1 + 1 > qa) ? __expf(-0.5f * s4[nt1][1]) : 0.0f;
            *(uint4*)&Pw[qrow * 64 + ((16 * kt2 + 4 * la3) ^ sw)] =
                make_uint4(f2tf32(e0), f2tf32(e1), f2tf32(e2), f2tf32(e3));
            e0 = (kg0     > qb8) ? __expf(-0.5f * s4[nt0][2]) : 0.0f;
            e1 = (kg0 + 1 > qb8) ? __expf(-0.5f * s4[nt0][3]) : 0.0f;
            e2 = (kg1     > qb8) ? __expf(-0.5f * s4[nt1][2]) : 0.0f;
            e3 = (kg1 + 1 > qb8) ? __expf(-0.5f * s4[nt1][3]) : 0.0f;
            *(uint4*)&Pw[(qrow + 8) * 64 + ((16 * kt2 + 4 * la3) ^ sw)] =
                make_uint4(f2tf32(e0), f2tf32(e1), f2tf32(e2), f2tf32(e3));
        }
        __syncwarp();   // Pw rows are warp-private

        cp_wait<1>();          // V(t) resident
        __syncthreads();

        // ---- PV: ctx += P @ V over 64 keys (all LDS.128) ----
        #pragma unroll
        for (int kt2 = 0; kt2 < 4; kt2++) {
            uint4 Pa = *(const uint4*)&Pw[qrow * 64 + ((16 * kt2 + 4 * la3) ^ sw)];
            uint4 Pb = *(const uint4*)&Pw[(qrow + 8) * 64 + ((16 * kt2 + 4 * la3) ^ sw)];
            #pragma unroll
            for (int nt = 0; nt < 8; nt++) {
                int vr = nt * 8 + l4;
                uint4 Vq = *(const uint4*)&Vp[vr * 64 + ((16 * kt2 + 4 * la3) ^ ((vr & 1) << 4))];
                mma8(ctx[nt], Pa.x, Pb.x, Pa.y, Pb.y, Vq.x, Vq.y);
                mma8(ctx[nt], Pa.z, Pb.z, Pa.w, Pb.w, Vq.z, Vq.w);
            }
        }

        __syncthreads();                       // all warps done reading Vp/Ps
        if (t + 1 < nT) FILL_V(t + 1);         // overlaps next QK
        cp_commit();
    }

    // Store ctx as tf32 in merged [B,S,H] layout
    uint32_t* Cb = C + (size_t)b * SS * HH + h * HD;
    #pragma unroll
    for (int nt = 0; nt < 8; nt++) {
        int r = q0 + qrow;
        int c = nt * 8 + 2 * la3;
        *(uint2*)&Cb[(size_t)r       * HH + c] = make_uint2(f2tf32(ctx[nt][0]), f2tf32(ctx[nt][1]));
        *(uint2*)&Cb[(size_t)(r + 8) * HH + c] = make_uint2(f2tf32(ctx[nt][2]), f2tf32(ctx[nt][3]));
    }
    #undef FILL_DK
    #undef FILL_V
}

static const int ATTN_SMEM = (3 * 64 * 64) * 4;                  // 49152 B
static const int BF3_SMEM  = (2 * 128 * 40 + 2 * 16 * 264) * 4;  // 74752 B

extern "C" void kernel_launch(void* const* d_in, const int* in_sizes, int n_in,
                              void* d_out, int out_size) {
    const float* x  = (const float*)d_in[0];
    const float* Wq = (const float*)d_in[1];
    const float* bq = (const float*)d_in[2];
    const float* Wk = (const float*)d_in[3];
    const float* bk = (const float*)d_in[4];
    const float* Wv = (const float*)d_in[5];
    const float* bv = (const float*)d_in[6];
    const float* Wo = (const float*)d_in[7];
    const float* bo = (const float*)d_in[8];
    float* out = (float*)d_out;

    uint32_t *pxTF, *pxHL, *pWdHL, *pWvTF, *pWoTF, *pDHL, *pVtP, *pC;
    float *pbd;
    cudaGetSymbolAddress((void**)&pxTF,  g_xTF);
    cudaGetSymbolAddress((void**)&pxHL,  g_xHL);
    cudaGetSymbolAddress((void**)&pWdHL, g_WdHL);
    cudaGetSymbolAddress((void**)&pWvTF, g_WvTF);
    cudaGetSymbolAddress((void**)&pWoTF, g_WoTF);
    cudaGetSymbolAddress((void**)&pbd,   g_bd);
    cudaGetSymbolAddress((void**)&pDHL,  g_DHL);
    cudaGetSymbolAddress((void**)&pVtP,  g_VtP);
    cudaGetSymbolAddress((void**)&pC,    g_C);

    static bool attr_set = false;
    if (!attr_set) {
        cudaFuncSetAttribute(attn_tc, cudaFuncAttributeMaxDynamicSharedMemorySize, ATTN_SMEM);
        cudaFuncSetAttribute(gemm_bf3, cudaFuncAttributeMaxDynamicSharedMemorySize, BF3_SMEM);
        attr_set = true;
    }

    // 1. prep
    prep_x  <<<(MM * HH / 4) / 256, 256>>>(x);
    prep_wd <<<(512 * 1024) / 256, 256>>>(Wq, Wk, bq, bk);
    prep_tf2<<<dim3((HH * HH / 4) / 256, 2), 256>>>(Wv, pWvTF, Wo, pWoTF);

    // 2. D = x @ Wd + bd (3xBF16) ; V = x @ Wv + bv (tf32, direct PHI VtP out)
    dim3 ggrid(HH / 128, MM / 128);
    gemm_bf3<<<ggrid, 256, BF3_SMEM>>>(pxHL, pWdHL, pbd, pDHL);
    gemm_tc<3><<<ggrid, 256>>>(pxTF, pWvTF, bv, pVtP);

    // 3. fused attention (LPT: qb slowest-varying, longest first)
    dim3 agrid(NH, BB, SS / 64);
    attn_tc<<<agrid, 128, ATTN_SMEM>>>(pDHL, pVtP, pC);

    // 4. out = ctx @ Wo + bo (tf32)
    gemm_tc<0><<<ggrid, 256>>>(pC, pWoTF, bo, out);
}